// round 1
// baseline (speedup 1.0000x reference)
#include <cuda_runtime.h>
#include <math.h>
#include <stdint.h>

// Problem constants
#define B_ 8
#define T_ 2048
#define D_ 1024
#define H_ 4
#define DK_ 256
#define DV_ 256
#define NH_ 2
#define KC_ 4
#define I_ 2816
#define EPS_ 1e-6f

#define MT_ (B_*T_)          // 16384 rows

// ---------------- scratch (device globals; no allocation allowed) ----------------
__device__ float g_es[B_*D_];
__device__ float g_ge[B_*D_];
__device__ float g_gx[MT_*D_];
__device__ float g_xf[MT_*D_];
__device__ float g_h [MT_*D_];
__device__ float g_qlin[MT_*D_];
__device__ float g_klin[MT_*2048];
__device__ float g_vlin[MT_*2048];
__device__ float g_qn[MT_*D_];          // [B,H,T,DK]
__device__ float g_kn[MT_*2048];        // [B,NH*H,T,DK]
__device__ float g_vn[MT_*2048];        // [B,NH*H,T,DV]
__device__ float g_beta[B_*NH_*H_*T_];
__device__ float g_eg[B_*H_*T_];
__device__ float g_o [MT_*D_];          // [B,T,H,DV]
__device__ float g_on[MT_*D_];
__device__ float g_x2[MT_*D_];
__device__ float g_h2[MT_*D_];
__device__ float g_gl[MT_*I_];
__device__ float g_ul[MT_*I_];
__device__ float g_m [MT_*I_];

// ---------------- helpers ----------------
__device__ __forceinline__ float sigmoidf_(float x){ return 1.f/(1.f+expf(-x)); }
__device__ __forceinline__ float softplusf_(float x){ return x>20.f? x : log1pf(expf(x)); }

__device__ __forceinline__ float blockReduce256(float v){
    __shared__ float sh[8];
    #pragma unroll
    for(int o=16;o;o>>=1) v += __shfl_xor_sync(0xffffffffu, v, o);
    if((threadIdx.x&31)==0) sh[threadIdx.x>>5] = v;
    __syncthreads();
    float s = 0.f;
    #pragma unroll
    for(int i=0;i<8;i++) s += sh[i];
    return s;
}

// ---------------- small warp-dot kernels ----------------
// es[b,i] = sum_j prev[b,j]*W[i,j]
__global__ void k_es(const float* __restrict__ prev, const float* __restrict__ W,
                     float* __restrict__ es){
    int b = blockIdx.y;
    int w = threadIdx.x>>5, l = threadIdx.x&31;
    int i = blockIdx.x*8 + w;
    const float* pr = prev + b*D_;
    const float* wr = W + (size_t)i*D_;
    float s=0.f;
    for(int j=l;j<D_;j+=32) s += pr[j]*wr[j];
    #pragma unroll
    for(int o=16;o;o>>=1) s += __shfl_xor_sync(0xffffffffu,s,o);
    if(!l) es[b*D_+i]=s;
}

// ge[b,i] = sum_j es[b,j]*Wg[i,D+j] + bias[i]
__global__ void k_ge(const float* __restrict__ es, const float* __restrict__ Wg,
                     const float* __restrict__ bias, float* __restrict__ ge){
    int b = blockIdx.y;
    int w = threadIdx.x>>5, l = threadIdx.x&31;
    int i = blockIdx.x*8 + w;
    const float* er = es + b*D_;
    const float* wr = Wg + (size_t)i*(2*D_) + D_;
    float s=0.f;
    for(int j=l;j<D_;j+=32) s += er[j]*wr[j];
    #pragma unroll
    for(int o=16;o;o>>=1) s += __shfl_xor_sync(0xffffffffu,s,o);
    if(!l) ge[b*D_+i] = s + bias[i];
}

// ---------------- SGEMM: C[M,N] = A[M,K] * B[N,K]^T (+ residual) ----------------
template<bool RES>
__global__ void __launch_bounds__(256)
sgemm_nt(int M, int N, int K,
         const float* __restrict__ A, int lda,
         const float* __restrict__ Bm, int ldb,
         const float* __restrict__ Res,
         float* __restrict__ C, int ldc){
    const int BK = 16;
    __shared__ float As[2][BK][128];
    __shared__ float Bs[2][BK][128];
    int tid = threadIdx.x;
    int rowBase = blockIdx.y*128, colBase = blockIdx.x*128;
    int tx = tid & 15, ty = tid >> 4;

    float acc[8][8];
    #pragma unroll
    for(int i=0;i<8;i++)
        #pragma unroll
        for(int j=0;j<8;j++) acc[i][j]=0.f;

    int nt = K / BK;

    // load tile 0
    float4 pa[2], pb[2];
    #pragma unroll
    for(int i=0;i<2;i++){
        int id = tid + i*256;
        int r = id>>2, c4 = id&3;
        pa[i] = *(const float4*)(A + (size_t)(rowBase+r)*lda + c4*4);
        pb[i] = *(const float4*)(Bm + (size_t)(colBase+r)*ldb + c4*4);
    }
    #pragma unroll
    for(int i=0;i<2;i++){
        int id = tid + i*256;
        int r = id>>2, c4 = id&3;
        As[0][c4*4+0][r]=pa[i].x; As[0][c4*4+1][r]=pa[i].y;
        As[0][c4*4+2][r]=pa[i].z; As[0][c4*4+3][r]=pa[i].w;
        Bs[0][c4*4+0][r]=pb[i].x; Bs[0][c4*4+1][r]=pb[i].y;
        Bs[0][c4*4+2][r]=pb[i].z; Bs[0][c4*4+3][r]=pb[i].w;
    }
    __syncthreads();

    for(int t=0;t<nt;t++){
        int cb = t&1, nb = cb^1;
        bool hn = (t+1<nt);
        if(hn){
            int kof = (t+1)*BK;
            #pragma unroll
            for(int i=0;i<2;i++){
                int id = tid + i*256;
                int r = id>>2, c4 = id&3;
                pa[i] = *(const float4*)(A + (size_t)(rowBase+r)*lda + kof + c4*4);
                pb[i] = *(const float4*)(Bm + (size_t)(colBase+r)*ldb + kof + c4*4);
            }
        }
        #pragma unroll
        for(int kk=0;kk<BK;kk++){
            float a8[8], b8[8];
            #pragma unroll
            for(int i=0;i<8;i++) a8[i]=As[cb][kk][ty*8+i];
            #pragma unroll
            for(int j=0;j<8;j++) b8[j]=Bs[cb][kk][tx*8+j];
            #pragma unroll
            for(int i=0;i<8;i++)
                #pragma unroll
                for(int j=0;j<8;j++) acc[i][j] += a8[i]*b8[j];
        }
        if(hn){
            #pragma unroll
            for(int i=0;i<2;i++){
                int id = tid + i*256;
                int r = id>>2, c4 = id&3;
                As[nb][c4*4+0][r]=pa[i].x; As[nb][c4*4+1][r]=pa[i].y;
                As[nb][c4*4+2][r]=pa[i].z; As[nb][c4*4+3][r]=pa[i].w;
                Bs[nb][c4*4+0][r]=pb[i].x; Bs[nb][c4*4+1][r]=pb[i].y;
                Bs[nb][c4*4+2][r]=pb[i].z; Bs[nb][c4*4+3][r]=pb[i].w;
            }
        }
        __syncthreads();
    }

    #pragma unroll
    for(int i=0;i<8;i++){
        int row = rowBase + ty*8 + i;
        #pragma unroll
        for(int j4=0;j4<2;j4++){
            int col = colBase + tx*8 + j4*4;
            float4 v = make_float4(acc[i][j4*4+0],acc[i][j4*4+1],acc[i][j4*4+2],acc[i][j4*4+3]);
            if(RES){
                float4 r = *(const float4*)(Res + (size_t)row*ldc + col);
                v.x+=r.x; v.y+=r.y; v.z+=r.z; v.w+=r.w;
            }
            *(float4*)(C + (size_t)row*ldc + col) = v;
        }
    }
}

// ---------------- elementwise fusion ----------------
__global__ void k_fuse(const float* __restrict__ x, const float* __restrict__ gx,
                       const float* __restrict__ ge, const float* __restrict__ es,
                       float* __restrict__ xf){
    size_t idx = (size_t)blockIdx.x*256 + threadIdx.x;
    int i = (int)(idx & (D_-1));
    int m = (int)(idx >> 10);
    int b = m >> 11;
    float g = sigmoidf_(gx[idx] + ge[b*D_+i]);
    float e = es[b*D_+i];
    xf[idx] = g*x[idx] + (1.f-g)*e;
}

// RMSNorm over D=1024
__global__ void k_rms(const float* __restrict__ in, const float* __restrict__ w,
                      float* __restrict__ out){
    int row = blockIdx.x, tid = threadIdx.x;
    const float4* ir = (const float4*)(in + (size_t)row*D_);
    float4 v = ir[tid];
    float ss = blockReduce256(v.x*v.x+v.y*v.y+v.z*v.z+v.w*v.w);
    float sc = rsqrtf(ss*(1.f/D_) + EPS_);
    float4 ww = ((const float4*)w)[tid];
    float4 o4 = make_float4(v.x*sc*ww.x, v.y*sc*ww.y, v.z*sc*ww.z, v.w*sc*ww.w);
    ((float4*)(out + (size_t)row*D_))[tid] = o4;
}

// beta + decay gate from h
__global__ void k_ba(const float* __restrict__ h, const float* __restrict__ bw,
                     const float* __restrict__ aw, const float* __restrict__ A_log,
                     const float* __restrict__ dtb,
                     float* __restrict__ beta, float* __restrict__ eg){
    int row = blockIdx.x;
    int b = row >> 11, t = row & (T_-1);
    int w = threadIdx.x>>5, l = threadIdx.x&31;
    const float* hr = h + (size_t)row*D_;
    {
        const float* wr = bw + (size_t)w*D_;
        float s=0.f;
        for(int j=l;j<D_;j+=32) s += hr[j]*wr[j];
        #pragma unroll
        for(int o=16;o;o>>=1) s += __shfl_xor_sync(0xffffffffu,s,o);
        if(!l){
            int i = w>>2, hh = w&3;
            beta[(( (b*NH_+i)*H_+hh )*T_) + t] = 2.f*sigmoidf_(s);
        }
    }
    if(w < H_){
        const float* ar = aw + (size_t)w*D_;
        float s=0.f;
        for(int j=l;j<D_;j+=32) s += hr[j]*ar[j];
        #pragma unroll
        for(int o=16;o;o>>=1) s += __shfl_xor_sync(0xffffffffu,s,o);
        if(!l){
            float g = -expf(A_log[w]) * softplusf_(s + dtb[w]);
            eg[(b*H_+w)*T_ + t] = expf(g);
        }
    }
}

// causal depthwise conv (K=4) + silu (+ optional L2 norm per head) + relayout
template<bool NORM>
__global__ void k_conv(const float* __restrict__ in, const float* __restrict__ cw,
                       float* __restrict__ out, int nheads){
    int t = blockIdx.x, hd = blockIdx.y, b = blockIdx.z, c = threadIdx.x;
    int C = nheads*256;
    int ch = hd*256 + c;
    const float* wp = cw + (size_t)ch*KC_;
    float acc = 0.f;
    #pragma unroll
    for(int j=0;j<KC_;j++){
        int tt = t - (KC_-1) + j;
        if(tt>=0) acc += in[((size_t)(b*T_+tt))*C + ch]*wp[j];
    }
    float s = acc * sigmoidf_(acc);
    float y;
    if(NORM){
        float ss = blockReduce256(s*s);
        y = s * rsqrtf(ss + EPS_);
    } else y = s;
    out[(((size_t)(b*nheads+hd)*T_)+t)*256 + c] = y;
}

// ---------------- gated delta-product scan ----------------
// grid: B*H*8 CTAs (each owns 32 V-columns), 256 threads.
// thread layout: warp w (0..7), lane l; col = w*4 + (l>>3); kseg = l&7 (32 k each)
__global__ void __launch_bounds__(256) k_scan(
    const float* __restrict__ qn, const float* __restrict__ kn,
    const float* __restrict__ vn, const float* __restrict__ beta,
    const float* __restrict__ eg, float* __restrict__ o){
    int cta = blockIdx.x;
    int ch = cta & 7;
    int hh = (cta>>3)&3;
    int b  = cta>>5;
    int vbase = ch*32;
    int tid = threadIdx.x;
    int w = tid>>5, l = tid&31;
    int col = w*4 + (l>>3);
    int kseg = l&7;
    int k0i = kseg*32;

    __shared__ float sq[2][256], sk0[2][256], sk1[2][256];
    __shared__ float sv0[2][32], sv1[2][32], ssc[2][4];

    float S[32];
    #pragma unroll
    for(int j=0;j<32;j++) S[j]=0.f;

    const float* qrow  = qn + (size_t)(b*H_+hh)*T_*256;
    const float* k0row = kn + (size_t)(b*8 + hh)*T_*256;
    const float* k1row = kn + (size_t)(b*8 + H_ + hh)*T_*256;
    const float* v0row = vn + (size_t)(b*8 + hh)*T_*256 + vbase;
    const float* v1row = vn + (size_t)(b*8 + H_ + hh)*T_*256 + vbase;
    const float* b0p = beta + ((b*NH_+0)*H_+hh)*T_;
    const float* b1p = beta + ((b*NH_+1)*H_+hh)*T_;
    const float* egp = eg + (b*H_+hh)*T_;

    // stage t=0
    sq [0][tid] = qrow[tid];
    sk0[0][tid] = k0row[tid];
    sk1[0][tid] = k1row[tid];
    if(tid<32) sv0[0][tid] = v0row[tid];
    else if(tid<64) sv1[0][tid-32] = v1row[tid-32];
    if(tid==64) ssc[0][0]=b0p[0];
    if(tid==65) ssc[0][1]=b1p[0];
    if(tid==66) ssc[0][2]=egp[0];
    __syncthreads();

    const float out_scale = rsqrtf((float)DK_);

    for(int t=0;t<T_;t++){
        int cb = t&1, nb = cb^1;
        bool hn = (t+1 < T_);
        float pq=0.f, pk0=0.f, pk1=0.f, pv=0.f, psc=0.f;
        if(hn){
            size_t off = (size_t)(t+1)*256;
            pq  = qrow [off+tid];
            pk0 = k0row[off+tid];
            pk1 = k1row[off+tid];
            if(tid<32) pv = v0row[off+tid];
            else if(tid<64) pv = v1row[off + tid-32];
            if(tid==64) psc = b0p[t+1];
            if(tid==65) psc = b1p[t+1];
            if(tid==66) psc = egp[t+1];
        }

        float egv = ssc[cb][2];
        float b0v = ssc[cb][0], b1v = ssc[cb][1];
        float v0c = sv0[cb][col], v1c = sv1[cb][col];

        #pragma unroll
        for(int j=0;j<32;j++) S[j] *= egv;

        float kr[32];
        // ---- householder 0 ----
        {
            const float4* kp = (const float4*)(&sk0[cb][k0i]);
            #pragma unroll
            for(int j=0;j<8;j++){ float4 k4 = kp[j];
                kr[j*4+0]=k4.x; kr[j*4+1]=k4.y; kr[j*4+2]=k4.z; kr[j*4+3]=k4.w; }
            float pred=0.f;
            #pragma unroll
            for(int j=0;j<32;j++) pred += S[j]*kr[j];
            pred += __shfl_xor_sync(0xffffffffu,pred,1);
            pred += __shfl_xor_sync(0xffffffffu,pred,2);
            pred += __shfl_xor_sync(0xffffffffu,pred,4);
            float u = (v0c - pred)*b0v;
            #pragma unroll
            for(int j=0;j<32;j++) S[j] += kr[j]*u;
        }
        // ---- householder 1 ----
        {
            const float4* kp = (const float4*)(&sk1[cb][k0i]);
            #pragma unroll
            for(int j=0;j<8;j++){ float4 k4 = kp[j];
                kr[j*4+0]=k4.x; kr[j*4+1]=k4.y; kr[j*4+2]=k4.z; kr[j*4+3]=k4.w; }
            float pred=0.f;
            #pragma unroll
            for(int j=0;j<32;j++) pred += S[j]*kr[j];
            pred += __shfl_xor_sync(0xffffffffu,pred,1);
            pred += __shfl_xor_sync(0xffffffffu,pred,2);
            pred += __shfl_xor_sync(0xffffffffu,pred,4);
            float u = (v1c - pred)*b1v;
            #pragma unroll
            for(int j=0;j<32;j++) S[j] += kr[j]*u;
        }
        // ---- output ----
        {
            const float4* qp = (const float4*)(&sq[cb][k0i]);
            float po=0.f;
            #pragma unroll
            for(int j=0;j<8;j++){ float4 q4 = qp[j];
                po += S[j*4+0]*q4.x + S[j*4+1]*q4.y + S[j*4+2]*q4.z + S[j*4+3]*q4.w; }
            po += __shfl_xor_sync(0xffffffffu,po,1);
            po += __shfl_xor_sync(0xffffffffu,po,2);
            po += __shfl_xor_sync(0xffffffffu,po,4);
            if(kseg==0)
                o[(((size_t)(b*T_+t))*H_ + hh)*256 + vbase + col] = po*out_scale;
        }

        if(hn){
            sq [nb][tid]=pq; sk0[nb][tid]=pk0; sk1[nb][tid]=pk1;
            if(tid<32) sv0[nb][tid]=pv;
            else if(tid<64) sv1[nb][tid-32]=pv;
            if(tid==64) ssc[nb][0]=psc;
            if(tid==65) ssc[nb][1]=psc;
            if(tid==66) ssc[nb][2]=psc;
        }
        __syncthreads();
    }
}

// per-head RMSNorm over DV=256
__global__ void k_onorm(const float* __restrict__ o, const float* __restrict__ w,
                        float* __restrict__ out){
    int row = blockIdx.x, tid = threadIdx.x;
    float v = o[(size_t)row*256 + tid];
    float ss = blockReduce256(v*v);
    out[(size_t)row*256 + tid] = v * rsqrtf(ss*(1.f/256.f) + EPS_) * w[tid];
}

__global__ void k_swiglu(const float* __restrict__ gl, const float* __restrict__ ul,
                         float* __restrict__ m, size_t n){
    size_t idx = (size_t)blockIdx.x*256 + threadIdx.x;
    if(idx < n){
        float g = gl[idx];
        m[idx] = g * sigmoidf_(g) * ul[idx];
    }
}

__global__ void k_last(const float* __restrict__ out, float* __restrict__ dst){
    int idx = blockIdx.x*256 + threadIdx.x; // B*D = 8192
    int b = idx >> 10, i = idx & (D_-1);
    dst[idx] = out[((size_t)(b*T_ + (T_-1)))*D_ + i];
}

// ---------------- launcher ----------------
extern "C" void kernel_launch(void* const* d_in, const int* in_sizes, int n_in,
                              void* d_out, int out_size){
    const float* x    = (const float*)d_in[0];
    const float* prev = (const float*)d_in[1];
    const float* spw  = (const float*)d_in[2];
    const float* sgw  = (const float*)d_in[3];
    const float* sgb  = (const float*)d_in[4];
    const float* anw  = (const float*)d_in[5];
    const float* qw   = (const float*)d_in[6];
    const float* kw   = (const float*)d_in[7];
    const float* vw   = (const float*)d_in[8];
    const float* bw   = (const float*)d_in[9];
    const float* aw   = (const float*)d_in[10];
    const float* Alog = (const float*)d_in[11];
    const float* dtb  = (const float*)d_in[12];
    const float* qcw  = (const float*)d_in[13];
    const float* kcw  = (const float*)d_in[14];
    const float* vcw  = (const float*)d_in[15];
    const float* onw  = (const float*)d_in[16];
    const float* ow   = (const float*)d_in[17];
    const float* mnw  = (const float*)d_in[18];
    const float* gw   = (const float*)d_in[19];
    const float* uw   = (const float*)d_in[20];
    const float* dw   = (const float*)d_in[21];
    float* out = (float*)d_out;

    float *es,*ge,*gx,*xf,*h,*qlin,*klin,*vlin,*qn,*kn,*vn,*beta,*eg,*ob,*on,*x2,*h2,*gl,*ul,*mm;
    cudaGetSymbolAddress((void**)&es, g_es);
    cudaGetSymbolAddress((void**)&ge, g_ge);
    cudaGetSymbolAddress((void**)&gx, g_gx);
    cudaGetSymbolAddress((void**)&xf, g_xf);
    cudaGetSymbolAddress((void**)&h,  g_h);
    cudaGetSymbolAddress((void**)&qlin, g_qlin);
    cudaGetSymbolAddress((void**)&klin, g_klin);
    cudaGetSymbolAddress((void**)&vlin, g_vlin);
    cudaGetSymbolAddress((void**)&qn, g_qn);
    cudaGetSymbolAddress((void**)&kn, g_kn);
    cudaGetSymbolAddress((void**)&vn, g_vn);
    cudaGetSymbolAddress((void**)&beta, g_beta);
    cudaGetSymbolAddress((void**)&eg, g_eg);
    cudaGetSymbolAddress((void**)&ob, g_o);
    cudaGetSymbolAddress((void**)&on, g_on);
    cudaGetSymbolAddress((void**)&x2, g_x2);
    cudaGetSymbolAddress((void**)&h2, g_h2);
    cudaGetSymbolAddress((void**)&gl, g_gl);
    cudaGetSymbolAddress((void**)&ul, g_ul);
    cudaGetSymbolAddress((void**)&mm, g_m);

    // ---- state fusion ----
    k_es<<<dim3(D_/8, B_), 256>>>(prev, spw, es);
    k_ge<<<dim3(D_/8, B_), 256>>>(es, sgw, sgb, ge);
    sgemm_nt<false><<<dim3(D_/128, MT_/128), 256>>>(MT_, D_, D_, x, D_, sgw, 2*D_, nullptr, gx, D_);
    k_fuse<<<MT_*D_/256, 256>>>(x, gx, ge, es, xf);

    // ---- attention sub-block ----
    k_rms<<<MT_, 256>>>(xf, anw, h);
    sgemm_nt<false><<<dim3(D_/128, MT_/128), 256>>>(MT_, D_,   D_, h, D_, qw, D_, nullptr, qlin, D_);
    sgemm_nt<false><<<dim3(2048/128, MT_/128), 256>>>(MT_, 2048, D_, h, D_, kw, D_, nullptr, klin, 2048);
    sgemm_nt<false><<<dim3(2048/128, MT_/128), 256>>>(MT_, 2048, D_, h, D_, vw, D_, nullptr, vlin, 2048);
    k_ba<<<MT_, 256>>>(h, bw, aw, Alog, dtb, beta, eg);
    k_conv<true ><<<dim3(T_, H_,      B_), 256>>>(qlin, qcw, qn, H_);
    k_conv<true ><<<dim3(T_, NH_*H_, B_), 256>>>(klin, kcw, kn, NH_*H_);
    k_conv<false><<<dim3(T_, NH_*H_, B_), 256>>>(vlin, vcw, vn, NH_*H_);

    k_scan<<<B_*H_*8, 256>>>(qn, kn, vn, beta, eg, ob);

    k_onorm<<<MT_*H_, 256>>>(ob, onw, on);
    sgemm_nt<true><<<dim3(D_/128, MT_/128), 256>>>(MT_, D_, D_, on, D_, ow, D_, xf, x2, D_);

    // ---- MLP ----
    k_rms<<<MT_, 256>>>(x2, mnw, h2);
    sgemm_nt<false><<<dim3(I_/128, MT_/128), 256>>>(MT_, I_, D_, h2, D_, gw, D_, nullptr, gl, I_);
    sgemm_nt<false><<<dim3(I_/128, MT_/128), 256>>>(MT_, I_, D_, h2, D_, uw, D_, nullptr, ul, I_);
    {
        size_t n = (size_t)MT_*I_;
        k_swiglu<<<(unsigned)((n+255)/256), 256>>>(gl, ul, mm, n);
    }
    sgemm_nt<true><<<dim3(D_/128, MT_/128), 256>>>(MT_, D_, I_, mm, I_, dw, I_, x2, out, D_);

    // ---- second output: final hidden state ----
    k_last<<<B_*D_/256, 256>>>(out, out + (size_t)MT_*D_);
}

// round 4
// speedup vs baseline: 1.3804x; 1.3804x over previous
#include <cuda_runtime.h>
#include <cuda_bf16.h>
#include <math.h>
#include <stdint.h>

// Problem constants
#define B_ 8
#define T_ 2048
#define D_ 1024
#define H_ 4
#define DK_ 256
#define DV_ 256
#define NH_ 2
#define KC_ 4
#define I_ 2816
#define EPS_ 1e-6f

#define MT_ (B_*T_)          // 16384 rows

// ---------------- scratch (device globals; no allocation allowed) ----------------
__device__ float g_es[B_*D_];
__device__ float g_ge[B_*D_];
__device__ float g_gx[MT_*D_];
__device__ float g_xf[MT_*D_];
__device__ float g_h [MT_*D_];
__device__ float g_qlin[MT_*D_];
__device__ float g_klin[MT_*2048];
__device__ float g_vlin[MT_*2048];
__device__ float g_qn[MT_*D_];          // [B,H,T,DK]
__device__ float g_kn[MT_*2048];        // [B,NH*H,T,DK]
__device__ float g_vn[MT_*2048];        // [B,NH*H,T,DV]
__device__ float g_beta[B_*NH_*H_*T_];
__device__ float g_eg[B_*H_*T_];
__device__ float g_o [MT_*D_];          // [B,T,H,DV]
__device__ float g_x2[MT_*D_];
__device__ float g_gl[MT_*I_];
__device__ float g_ul[MT_*I_];

// bf16 hi/lo split scratch (activations)
__device__ __nv_bfloat16 g_xh[MT_*D_],  g_xl[MT_*D_];
__device__ __nv_bfloat16 g_hh[MT_*D_],  g_hl[MT_*D_];
__device__ __nv_bfloat16 g_onh[MT_*D_], g_onl[MT_*D_];
__device__ __nv_bfloat16 g_h2h[MT_*D_], g_h2l[MT_*D_];
__device__ __nv_bfloat16 g_mh[MT_*I_],  g_ml[MT_*I_];
// bf16 hi/lo weights
__device__ __nv_bfloat16 g_wsgh[D_*D_],   g_wsgl[D_*D_];
__device__ __nv_bfloat16 g_wqh[D_*D_],    g_wql[D_*D_];
__device__ __nv_bfloat16 g_wkh[2048*D_],  g_wkl[2048*D_];
__device__ __nv_bfloat16 g_wvh[2048*D_],  g_wvl[2048*D_];
__device__ __nv_bfloat16 g_woh[D_*D_],    g_wol[D_*D_];
__device__ __nv_bfloat16 g_wgh[I_*D_],    g_wgl[I_*D_];
__device__ __nv_bfloat16 g_wuh[I_*D_],    g_wul[I_*D_];
__device__ __nv_bfloat16 g_wdh[D_*I_],    g_wdl[D_*I_];

// ---------------- helpers ----------------
__device__ __forceinline__ float sigmoidf_(float x){ return 1.f/(1.f+expf(-x)); }
__device__ __forceinline__ float softplusf_(float x){ return x>20.f? x : log1pf(expf(x)); }

__device__ __forceinline__ float blockReduce256(float v){
    __shared__ float sh[8];
    #pragma unroll
    for(int o=16;o;o>>=1) v += __shfl_xor_sync(0xffffffffu, v, o);
    if((threadIdx.x&31)==0) sh[threadIdx.x>>5] = v;
    __syncthreads();
    float s = 0.f;
    #pragma unroll
    for(int i=0;i<8;i++) s += sh[i];
    return s;
}

__device__ __forceinline__ uint32_t smem_u32(const void* p){
    uint32_t a;
    asm("{ .reg .u64 t; cvta.to.shared.u64 t, %1; cvt.u32.u64 %0, t; }" : "=r"(a) : "l"(p));
    return a;
}
__device__ __forceinline__ void cp16(uint32_t s, const void* g){
    asm volatile("cp.async.cg.shared.global [%0], [%1], 16;" :: "r"(s), "l"(g));
}
__device__ __forceinline__ void cp_commit(){
    asm volatile("cp.async.commit_group;" ::: "memory");
}
template<int N>
__device__ __forceinline__ void cp_wait(){
    asm volatile("cp.async.wait_group %0;" :: "n"(N) : "memory");
}
__device__ __forceinline__ void ldm_x4(uint32_t* r, uint32_t addr){
    asm volatile("ldmatrix.sync.aligned.m8n8.x4.shared.b16 {%0,%1,%2,%3}, [%4];"
        : "=r"(r[0]), "=r"(r[1]), "=r"(r[2]), "=r"(r[3]) : "r"(addr));
}
__device__ __forceinline__ void mma16816(float* d, const uint32_t* a, const uint32_t* b){
    asm volatile("mma.sync.aligned.m16n8k16.row.col.f32.bf16.bf16.f32 "
        "{%0,%1,%2,%3}, {%4,%5,%6,%7}, {%8,%9}, {%0,%1,%2,%3};"
        : "+f"(d[0]), "+f"(d[1]), "+f"(d[2]), "+f"(d[3])
        : "r"(a[0]), "r"(a[1]), "r"(a[2]), "r"(a[3]), "r"(b[0]), "r"(b[1]));
}

// ---------------- HMMA bf16 3-term GEMM ----------------
// C[M,N] = A[M,K]*B[N,K]^T fp32-accurate via bf16 split: ah*bh + al*bh + ah*bl
// CTA tile 128x128, BK=32, 8 warps (4x2), warp tile 32x64, double-buffered cp.async.
#define BM 128
#define BN 128
#define BKg 32
#define ASTR 40   // bf16 row stride in smem (80B) -> conflict-free ldmatrix

template<bool RES>
__global__ void __launch_bounds__(256,2)
hm_gemm(const __nv_bfloat16* __restrict__ Ah, const __nv_bfloat16* __restrict__ Al,
        const __nv_bfloat16* __restrict__ Bh, const __nv_bfloat16* __restrict__ Bl,
        const float* __restrict__ Res, float* __restrict__ C, int K, int ldc)
{
    __shared__ __align__(16) __nv_bfloat16 sA[2][BM*ASTR];
    __shared__ __align__(16) __nv_bfloat16 sB[2][BN*ASTR];

    int tid = threadIdx.x, wid = tid>>5, lane = tid&31;
    int rowBase = blockIdx.y*BM, colBase = blockIdx.x*BN;
    int wr = wid & 3, wc = wid >> 2;
    int mBase = wr*32, nBase = wc*64;

    int nk = K >> 5;          // K/32 chunks per segment
    int nIter = 3*nk;

    float acc[2][8][4];
    #pragma unroll
    for(int mi=0;mi<2;mi++)
        #pragma unroll
        for(int ni=0;ni<8;ni++)
            #pragma unroll
            for(int q=0;q<4;q++) acc[mi][ni][q]=0.f;

    // loader indices: 512 16B-chunks per matrix, 2 per thread
    int lr = tid >> 2;          // row (0..63 with j offset)
    int lc = tid & 3;           // 16B-chunk within 32-col row

    uint32_t aS[2][2], bS[2][2];  // smem dst addresses per buf per j
    #pragma unroll
    for(int j=0;j<2;j++){
        int r = lr + j*64;
        #pragma unroll
        for(int bf=0; bf<2; bf++){
            aS[bf][j] = smem_u32(&sA[bf][r*ASTR + lc*8]);
            bS[bf][j] = smem_u32(&sB[bf][r*ASTR + lc*8]);
        }
    }

    auto stage = [&](int it, int buf){
        int seg = it / nk, cc = it - seg*nk;
        const __nv_bfloat16* As = (seg==1)? Al : Ah;
        const __nv_bfloat16* Bs = (seg==2)? Bl : Bh;
        int k0 = cc<<5;
        #pragma unroll
        for(int j=0;j<2;j++){
            int r = lr + j*64;
            cp16(aS[buf][j], As + (size_t)(rowBase+r)*K + k0 + lc*8);
            cp16(bS[buf][j], Bs + (size_t)(colBase+r)*K + k0 + lc*8);
        }
        cp_commit();
    };

    stage(0, 0);

    // precompute ldmatrix smem offsets (lane-dependent, buf-dependent base)
    uint32_t aL[2], bL[2];
    {
        int arow = mBase + (lane&15);
        int acol = (lane>>4)<<3;
        int brow = nBase + (lane&7) + (((lane>>4)&1)<<3);
        int bcol = ((lane>>3)&1)<<3;
        #pragma unroll
        for(int bf=0; bf<2; bf++){
            aL[bf] = smem_u32(&sA[bf][arow*ASTR + acol]);
            bL[bf] = smem_u32(&sB[bf][brow*ASTR + bcol]);
        }
    }

    for(int it=0; it<nIter; it++){
        int buf = it & 1;
        if(it+1 < nIter) stage(it+1, buf^1);
        if(it+1 < nIter) cp_wait<1>(); else cp_wait<0>();
        __syncthreads();

        #pragma unroll
        for(int ks=0; ks<2; ks++){
            uint32_t af[2][4], bfr[8][2];
            #pragma unroll
            for(int mi=0;mi<2;mi++)
                ldm_x4(af[mi], aL[buf] + (uint32_t)((mi*16*ASTR + ks*16)*2));
            #pragma unroll
            for(int n4=0;n4<4;n4++){
                uint32_t r4[4];
                ldm_x4(r4, bL[buf] + (uint32_t)((n4*16*ASTR + ks*16)*2));
                bfr[n4*2+0][0]=r4[0]; bfr[n4*2+0][1]=r4[1];
                bfr[n4*2+1][0]=r4[2]; bfr[n4*2+1][1]=r4[3];
            }
            #pragma unroll
            for(int mi=0;mi<2;mi++)
                #pragma unroll
                for(int ni=0;ni<8;ni++)
                    mma16816(acc[mi][ni], af[mi], bfr[ni]);
        }
        __syncthreads();
    }

    // epilogue
    int qr = lane>>2, qc = lane&3;
    #pragma unroll
    for(int mi=0;mi<2;mi++){
        #pragma unroll
        for(int ni=0;ni<8;ni++){
            int row0 = rowBase + mBase + mi*16 + qr;
            int col  = colBase + nBase + ni*8 + qc*2;
            float2 v0 = make_float2(acc[mi][ni][0], acc[mi][ni][1]);
            float2 v1 = make_float2(acc[mi][ni][2], acc[mi][ni][3]);
            if(RES){
                float2 r0 = *(const float2*)(Res + (size_t)row0*ldc + col);
                float2 r1 = *(const float2*)(Res + (size_t)(row0+8)*ldc + col);
                v0.x+=r0.x; v0.y+=r0.y; v1.x+=r1.x; v1.y+=r1.y;
            }
            *(float2*)(C + (size_t)row0*ldc + col) = v0;
            *(float2*)(C + (size_t)(row0+8)*ldc + col) = v1;
        }
    }
}

// ---------------- hi/lo conversion (rowwise, strided source) ----------------
__global__ void k_cvt(const float* __restrict__ in, int ld, int cols,
                      __nv_bfloat16* __restrict__ hi, __nv_bfloat16* __restrict__ lo){
    int r = blockIdx.x;
    const float* ip = in + (size_t)r*ld;
    __nv_bfloat16* hp = hi + (size_t)r*cols;
    __nv_bfloat16* lp = lo + (size_t)r*cols;
    for(int c = threadIdx.x*4; c < cols; c += 1024){
        float4 v = *(const float4*)(ip + c);
        __nv_bfloat16 h0=__float2bfloat16(v.x), h1=__float2bfloat16(v.y);
        __nv_bfloat16 h2=__float2bfloat16(v.z), h3=__float2bfloat16(v.w);
        *(__nv_bfloat162*)(hp+c)   = __nv_bfloat162(h0,h1);
        *(__nv_bfloat162*)(hp+c+2) = __nv_bfloat162(h2,h3);
        *(__nv_bfloat162*)(lp+c)   = __nv_bfloat162(
            __float2bfloat16(v.x-__bfloat162float(h0)), __float2bfloat16(v.y-__bfloat162float(h1)));
        *(__nv_bfloat162*)(lp+c+2) = __nv_bfloat162(
            __float2bfloat16(v.z-__bfloat162float(h2)), __float2bfloat16(v.w-__bfloat162float(h3)));
    }
}

// ---------------- small warp-dot kernels ----------------
__global__ void k_es(const float* __restrict__ prev, const float* __restrict__ W,
                     float* __restrict__ es){
    int b = blockIdx.y;
    int w = threadIdx.x>>5, l = threadIdx.x&31;
    int i = blockIdx.x*8 + w;
    const float* pr = prev + b*D_;
    const float* wr = W + (size_t)i*D_;
    float s=0.f;
    for(int j=l;j<D_;j+=32) s += pr[j]*wr[j];
    #pragma unroll
    for(int o=16;o;o>>=1) s += __shfl_xor_sync(0xffffffffu,s,o);
    if(!l) es[b*D_+i]=s;
}

__global__ void k_ge(const float* __restrict__ es, const float* __restrict__ Wg,
                     const float* __restrict__ bias, float* __restrict__ ge){
    int b = blockIdx.y;
    int w = threadIdx.x>>5, l = threadIdx.x&31;
    int i = blockIdx.x*8 + w;
    const float* er = es + b*D_;
    const float* wr = Wg + (size_t)i*(2*D_) + D_;
    float s=0.f;
    for(int j=l;j<D_;j+=32) s += er[j]*wr[j];
    #pragma unroll
    for(int o=16;o;o>>=1) s += __shfl_xor_sync(0xffffffffu,s,o);
    if(!l) ge[b*D_+i] = s + bias[i];
}

// ---------------- elementwise fusion ----------------
__global__ void k_fuse(const float* __restrict__ x, const float* __restrict__ gx,
                       const float* __restrict__ ge, const float* __restrict__ es,
                       float* __restrict__ xf){
    size_t idx = (size_t)blockIdx.x*256 + threadIdx.x;
    int i = (int)(idx & (D_-1));
    int m = (int)(idx >> 10);
    int b = m >> 11;
    float g = sigmoidf_(gx[idx] + ge[b*D_+i]);
    float e = es[b*D_+i];
    xf[idx] = g*x[idx] + (1.f-g)*e;
}

// RMSNorm over D=1024: optional fp32 out + hi/lo bf16 out
template<bool F32OUT>
__global__ void k_rms2(const float* __restrict__ in, const float* __restrict__ w,
                       float* __restrict__ out,
                       __nv_bfloat16* __restrict__ hi, __nv_bfloat16* __restrict__ lo){
    int row = blockIdx.x, tid = threadIdx.x;
    const float4* ir = (const float4*)(in + (size_t)row*D_);
    float4 v = ir[tid];
    float ss = blockReduce256(v.x*v.x+v.y*v.y+v.z*v.z+v.w*v.w);
    float sc = rsqrtf(ss*(1.f/D_) + EPS_);
    float4 ww = ((const float4*)w)[tid];
    float4 y = make_float4(v.x*sc*ww.x, v.y*sc*ww.y, v.z*sc*ww.z, v.w*sc*ww.w);
    if(F32OUT) ((float4*)(out + (size_t)row*D_))[tid] = y;
    int c = tid*4;
    __nv_bfloat16* hp = hi + (size_t)row*D_;
    __nv_bfloat16* lp = lo + (size_t)row*D_;
    __nv_bfloat16 h0=__float2bfloat16(y.x), h1=__float2bfloat16(y.y);
    __nv_bfloat16 h2=__float2bfloat16(y.z), h3=__float2bfloat16(y.w);
    *(__nv_bfloat162*)(hp+c)   = __nv_bfloat162(h0,h1);
    *(__nv_bfloat162*)(hp+c+2) = __nv_bfloat162(h2,h3);
    *(__nv_bfloat162*)(lp+c)   = __nv_bfloat162(
        __float2bfloat16(y.x-__bfloat162float(h0)), __float2bfloat16(y.y-__bfloat162float(h1)));
    *(__nv_bfloat162*)(lp+c+2) = __nv_bfloat162(
        __float2bfloat16(y.z-__bfloat162float(h2)), __float2bfloat16(y.w-__bfloat162float(h3)));
}

// beta + decay gate from h
__global__ void k_ba(const float* __restrict__ h, const float* __restrict__ bw,
                     const float* __restrict__ aw, const float* __restrict__ A_log,
                     const float* __restrict__ dtb,
                     float* __restrict__ beta, float* __restrict__ eg){
    int row = blockIdx.x;
    int b = row >> 11, t = row & (T_-1);
    int w = threadIdx.x>>5, l = threadIdx.x&31;
    const float* hr = h + (size_t)row*D_;
    {
        const float* wr = bw + (size_t)w*D_;
        float s=0.f;
        for(int j=l;j<D_;j+=32) s += hr[j]*wr[j];
        #pragma unroll
        for(int o=16;o;o>>=1) s += __shfl_xor_sync(0xffffffffu,s,o);
        if(!l){
            int i = w>>2, hh = w&3;
            beta[(( (b*NH_+i)*H_+hh )*T_) + t] = 2.f*sigmoidf_(s);
        }
    }
    if(w < H_){
        const float* ar = aw + (size_t)w*D_;
        float s=0.f;
        for(int j=l;j<D_;j+=32) s += hr[j]*ar[j];
        #pragma unroll
        for(int o=16;o;o>>=1) s += __shfl_xor_sync(0xffffffffu,s,o);
        if(!l){
            float g = -expf(A_log[w]) * softplusf_(s + dtb[w]);
            eg[(b*H_+w)*T_ + t] = expf(g);
        }
    }
}

// causal depthwise conv (K=4) + silu (+ optional L2 norm per head) + relayout
template<bool NORM>
__global__ void k_conv(const float* __restrict__ in, const float* __restrict__ cw,
                       float* __restrict__ out, int nheads){
    int t = blockIdx.x, hd = blockIdx.y, b = blockIdx.z, c = threadIdx.x;
    int C = nheads*256;
    int ch = hd*256 + c;
    const float* wp = cw + (size_t)ch*KC_;
    float acc = 0.f;
    #pragma unroll
    for(int j=0;j<KC_;j++){
        int tt = t - (KC_-1) + j;
        if(tt>=0) acc += in[((size_t)(b*T_+tt))*C + ch]*wp[j];
    }
    float s = acc * sigmoidf_(acc);
    float y;
    if(NORM){
        float ss = blockReduce256(s*s);
        y = s * rsqrtf(ss + EPS_);
    } else y = s;
    out[(((size_t)(b*nheads+hd)*T_)+t)*256 + c] = y;
}

// ---------------- gated delta-product scan ----------------
__global__ void __launch_bounds__(256) k_scan(
    const float* __restrict__ qn, const float* __restrict__ kn,
    const float* __restrict__ vn, const float* __restrict__ beta,
    const float* __restrict__ eg, float* __restrict__ o){
    int cta = blockIdx.x;
    int ch = cta & 7;
    int hh = (cta>>3)&3;
    int b  = cta>>5;
    int vbase = ch*32;
    int tid = threadIdx.x;
    int w = tid>>5, l = tid&31;
    int col = w*4 + (l>>3);
    int kseg = l&7;
    int k0i = kseg*32;

    __shared__ float sq[2][256], sk0[2][256], sk1[2][256];
    __shared__ float sv0[2][32], sv1[2][32], ssc[2][4];

    float S[32];
    #pragma unroll
    for(int j=0;j<32;j++) S[j]=0.f;

    const float* qrow  = qn + (size_t)(b*H_+hh)*T_*256;
    const float* k0row = kn + (size_t)(b*8 + hh)*T_*256;
    const float* k1row = kn + (size_t)(b*8 + H_ + hh)*T_*256;
    const float* v0row = vn + (size_t)(b*8 + hh)*T_*256 + vbase;
    const float* v1row = vn + (size_t)(b*8 + H_ + hh)*T_*256 + vbase;
    const float* b0p = beta + ((b*NH_+0)*H_+hh)*T_;
    const float* b1p = beta + ((b*NH_+1)*H_+hh)*T_;
    const float* egp = eg + (b*H_+hh)*T_;

    sq [0][tid] = qrow[tid];
    sk0[0][tid] = k0row[tid];
    sk1[0][tid] = k1row[tid];
    if(tid<32) sv0[0][tid] = v0row[tid];
    else if(tid<64) sv1[0][tid-32] = v1row[tid-32];
    if(tid==64) ssc[0][0]=b0p[0];
    if(tid==65) ssc[0][1]=b1p[0];
    if(tid==66) ssc[0][2]=egp[0];
    __syncthreads();

    const float out_scale = rsqrtf((float)DK_);

    for(int t=0;t<T_;t++){
        int cb = t&1, nb = cb^1;
        bool hn = (t+1 < T_);
        float pq=0.f, pk0=0.f, pk1=0.f, pv=0.f, psc=0.f;
        if(hn){
            size_t off = (size_t)(t+1)*256;
            pq  = qrow [off+tid];
            pk0 = k0row[off+tid];
            pk1 = k1row[off+tid];
            if(tid<32) pv = v0row[off+tid];
            else if(tid<64) pv = v1row[off + tid-32];
            if(tid==64) psc = b0p[t+1];
            if(tid==65) psc = b1p[t+1];
            if(tid==66) psc = egp[t+1];
        }

        float egv = ssc[cb][2];
        float b0v = ssc[cb][0], b1v = ssc[cb][1];
        float v0c = sv0[cb][col], v1c = sv1[cb][col];

        #pragma unroll
        for(int j=0;j<32;j++) S[j] *= egv;

        float kr[32];
        {
            const float4* kp = (const float4*)(&sk0[cb][k0i]);
            #pragma unroll
            for(int j=0;j<8;j++){ float4 k4 = kp[j];
                kr[j*4+0]=k4.x; kr[j*4+1]=k4.y; kr[j*4+2]=k4.z; kr[j*4+3]=k4.w; }
            float pred=0.f;
            #pragma unroll
            for(int j=0;j<32;j++) pred += S[j]*kr[j];
            pred += __shfl_xor_sync(0xffffffffu,pred,1);
            pred += __shfl_xor_sync(0xffffffffu,pred,2);
            pred += __shfl_xor_sync(0xffffffffu,pred,4);
            float u = (v0c - pred)*b0v;
            #pragma unroll
            for(int j=0;j<32;j++) S[j] += kr[j]*u;
        }
        {
            const float4* kp = (const float4*)(&sk1[cb][k0i]);
            #pragma unroll
            for(int j=0;j<8;j++){ float4 k4 = kp[j];
                kr[j*4+0]=k4.x; kr[j*4+1]=k4.y; kr[j*4+2]=k4.z; kr[j*4+3]=k4.w; }
            float pred=0.f;
            #pragma unroll
            for(int j=0;j<32;j++) pred += S[j]*kr[j];
            pred += __shfl_xor_sync(0xffffffffu,pred,1);
            pred += __shfl_xor_sync(0xffffffffu,pred,2);
            pred += __shfl_xor_sync(0xffffffffu,pred,4);
            float u = (v1c - pred)*b1v;
            #pragma unroll
            for(int j=0;j<32;j++) S[j] += kr[j]*u;
        }
        {
            const float4* qp = (const float4*)(&sq[cb][k0i]);
            float po=0.f;
            #pragma unroll
            for(int j=0;j<8;j++){ float4 q4 = qp[j];
                po += S[j*4+0]*q4.x + S[j*4+1]*q4.y + S[j*4+2]*q4.z + S[j*4+3]*q4.w; }
            po += __shfl_xor_sync(0xffffffffu,po,1);
            po += __shfl_xor_sync(0xffffffffu,po,2);
            po += __shfl_xor_sync(0xffffffffu,po,4);
            if(kseg==0)
                o[(((size_t)(b*T_+t))*H_ + hh)*256 + vbase + col] = po*out_scale;
        }

        if(hn){
            sq [nb][tid]=pq; sk0[nb][tid]=pk0; sk1[nb][tid]=pk1;
            if(tid<32) sv0[nb][tid]=pv;
            else if(tid<64) sv1[nb][tid-32]=pv;
            if(tid==64) ssc[nb][0]=psc;
            if(tid==65) ssc[nb][1]=psc;
            if(tid==66) ssc[nb][2]=psc;
        }
        __syncthreads();
    }
}

// per-head RMSNorm over DV=256 -> hi/lo bf16
__global__ void k_onorm(const float* __restrict__ o, const float* __restrict__ w,
                        __nv_bfloat16* __restrict__ hi, __nv_bfloat16* __restrict__ lo){
    int row = blockIdx.x, tid = threadIdx.x;
    float v = o[(size_t)row*256 + tid];
    float ss = blockReduce256(v*v);
    float y = v * rsqrtf(ss*(1.f/256.f) + EPS_) * w[tid];
    __nv_bfloat16 h = __float2bfloat16(y);
    hi[(size_t)row*256 + tid] = h;
    lo[(size_t)row*256 + tid] = __float2bfloat16(y - __bfloat162float(h));
}

__global__ void k_swiglu_cvt(const float* __restrict__ gl, const float* __restrict__ ul,
                             __nv_bfloat16* __restrict__ mh, __nv_bfloat16* __restrict__ ml,
                             size_t n4){
    size_t i4 = (size_t)blockIdx.x*256 + threadIdx.x;
    if(i4 < n4){
        size_t c = i4*4;
        float4 g4 = *(const float4*)(gl + c);
        float4 u4 = *(const float4*)(ul + c);
        float m0 = g4.x*sigmoidf_(g4.x)*u4.x;
        float m1 = g4.y*sigmoidf_(g4.y)*u4.y;
        float m2 = g4.z*sigmoidf_(g4.z)*u4.z;
        float m3 = g4.w*sigmoidf_(g4.w)*u4.w;
        __nv_bfloat16 h0=__float2bfloat16(m0), h1=__float2bfloat16(m1);
        __nv_bfloat16 h2=__float2bfloat16(m2), h3=__float2bfloat16(m3);
        *(__nv_bfloat162*)(mh+c)   = __nv_bfloat162(h0,h1);
        *(__nv_bfloat162*)(mh+c+2) = __nv_bfloat162(h2,h3);
        *(__nv_bfloat162*)(ml+c)   = __nv_bfloat162(
            __float2bfloat16(m0-__bfloat162float(h0)), __float2bfloat16(m1-__bfloat162float(h1)));
        *(__nv_bfloat162*)(ml+c+2) = __nv_bfloat162(
            __float2bfloat16(m2-__bfloat162float(h2)), __float2bfloat16(m3-__bfloat162float(h3)));
    }
}

__global__ void k_last(const float* __restrict__ out, float* __restrict__ dst){
    int idx = blockIdx.x*256 + threadIdx.x; // B*D = 8192
    int b = idx >> 10, i = idx & (D_-1);
    dst[idx] = out[((size_t)(b*T_ + (T_-1)))*D_ + i];
}

// ---------------- launcher ----------------
extern "C" void kernel_launch(void* const* d_in, const int* in_sizes, int n_in,
                              void* d_out, int out_size){
    const float* x    = (const float*)d_in[0];
    const float* prev = (const float*)d_in[1];
    const float* spw  = (const float*)d_in[2];
    const float* sgw  = (const float*)d_in[3];
    const float* sgb  = (const float*)d_in[4];
    const float* anw  = (const float*)d_in[5];
    const float* qw   = (const float*)d_in[6];
    const float* kw   = (const float*)d_in[7];
    const float* vw   = (const float*)d_in[8];
    const float* bw   = (const float*)d_in[9];
    const float* aw   = (const float*)d_in[10];
    const float* Alog = (const float*)d_in[11];
    const float* dtb  = (const float*)d_in[12];
    const float* qcw  = (const float*)d_in[13];
    const float* kcw  = (const float*)d_in[14];
    const float* vcw  = (const float*)d_in[15];
    const float* onw  = (const float*)d_in[16];
    const float* ow   = (const float*)d_in[17];
    const float* mnw  = (const float*)d_in[18];
    const float* gw   = (const float*)d_in[19];
    const float* uw   = (const float*)d_in[20];
    const float* dw   = (const float*)d_in[21];
    float* out = (float*)d_out;

    float *es,*ge,*gx,*xf,*h,*qlin,*klin,*vlin,*qn,*kn,*vn,*beta,*eg,*ob,*x2,*gl,*ul;
    cudaGetSymbolAddress((void**)&es, g_es);
    cudaGetSymbolAddress((void**)&ge, g_ge);
    cudaGetSymbolAddress((void**)&gx, g_gx);
    cudaGetSymbolAddress((void**)&xf, g_xf);
    cudaGetSymbolAddress((void**)&h,  g_h);
    cudaGetSymbolAddress((void**)&qlin, g_qlin);
    cudaGetSymbolAddress((void**)&klin, g_klin);
    cudaGetSymbolAddress((void**)&vlin, g_vlin);
    cudaGetSymbolAddress((void**)&qn, g_qn);
    cudaGetSymbolAddress((void**)&kn, g_kn);
    cudaGetSymbolAddress((void**)&vn, g_vn);
    cudaGetSymbolAddress((void**)&beta, g_beta);
    cudaGetSymbolAddress((void**)&eg, g_eg);
    cudaGetSymbolAddress((void**)&ob, g_o);
    cudaGetSymbolAddress((void**)&x2, g_x2);
    cudaGetSymbolAddress((void**)&gl, g_gl);
    cudaGetSymbolAddress((void**)&ul, g_ul);

    __nv_bfloat16 *xh,*xl,*hh,*hl,*onh,*onl,*h2h,*h2l,*mh,*ml;
    __nv_bfloat16 *wsgh,*wsgl,*wqh,*wql,*wkh,*wkl,*wvh,*wvl,*woh,*wol,*wgh,*wgl,*wuh,*wul,*wdh,*wdl;
    cudaGetSymbolAddress((void**)&xh, g_xh);   cudaGetSymbolAddress((void**)&xl, g_xl);
    cudaGetSymbolAddress((void**)&hh, g_hh);   cudaGetSymbolAddress((void**)&hl, g_hl);
    cudaGetSymbolAddress((void**)&onh, g_onh); cudaGetSymbolAddress((void**)&onl, g_onl);
    cudaGetSymbolAddress((void**)&h2h, g_h2h); cudaGetSymbolAddress((void**)&h2l, g_h2l);
    cudaGetSymbolAddress((void**)&mh, g_mh);   cudaGetSymbolAddress((void**)&ml, g_ml);
    cudaGetSymbolAddress((void**)&wsgh, g_wsgh); cudaGetSymbolAddress((void**)&wsgl, g_wsgl);
    cudaGetSymbolAddress((void**)&wqh, g_wqh);   cudaGetSymbolAddress((void**)&wql, g_wql);
    cudaGetSymbolAddress((void**)&wkh, g_wkh);   cudaGetSymbolAddress((void**)&wkl, g_wkl);
    cudaGetSymbolAddress((void**)&wvh, g_wvh);   cudaGetSymbolAddress((void**)&wvl, g_wvl);
    cudaGetSymbolAddress((void**)&woh, g_woh);   cudaGetSymbolAddress((void**)&wol, g_wol);
    cudaGetSymbolAddress((void**)&wgh, g_wgh);   cudaGetSymbolAddress((void**)&wgl, g_wgl);
    cudaGetSymbolAddress((void**)&wuh, g_wuh);   cudaGetSymbolAddress((void**)&wul, g_wul);
    cudaGetSymbolAddress((void**)&wdh, g_wdh);   cudaGetSymbolAddress((void**)&wdl, g_wdl);

    // ---- weight + input conversions ----
    k_cvt<<<1024, 256>>>(sgw, 2*D_, D_, wsgh, wsgl);   // first D cols of state_gate_w
    k_cvt<<<MT_, 256>>>(x, D_, D_, xh, xl);
    k_cvt<<<1024, 256>>>(qw, D_, D_, wqh, wql);
    k_cvt<<<2048, 256>>>(kw, D_, D_, wkh, wkl);
    k_cvt<<<2048, 256>>>(vw, D_, D_, wvh, wvl);
    k_cvt<<<1024, 256>>>(ow, D_, D_, woh, wol);
    k_cvt<<<I_, 256>>>(gw, D_, D_, wgh, wgl);
    k_cvt<<<I_, 256>>>(uw, D_, D_, wuh, wul);
    k_cvt<<<1024, 256>>>(dw, I_, I_, wdh, wdl);

    // ---- state fusion ----
    k_es<<<dim3(D_/8, B_), 256>>>(prev, spw, es);
    k_ge<<<dim3(D_/8, B_), 256>>>(es, sgw, sgb, ge);
    hm_gemm<false><<<dim3(D_/BN, MT_/BM), 256>>>(xh, xl, wsgh, wsgl, nullptr, gx, D_, D_);
    k_fuse<<<MT_*D_/256, 256>>>(x, gx, ge, es, xf);

    // ---- attention sub-block ----
    k_rms2<true><<<MT_, 256>>>(xf, anw, h, hh, hl);
    hm_gemm<false><<<dim3(D_/BN, MT_/BM), 256>>>(hh, hl, wqh, wql, nullptr, qlin, D_, D_);
    hm_gemm<false><<<dim3(2048/BN, MT_/BM), 256>>>(hh, hl, wkh, wkl, nullptr, klin, D_, 2048);
    hm_gemm<false><<<dim3(2048/BN, MT_/BM), 256>>>(hh, hl, wvh, wvl, nullptr, vlin, D_, 2048);
    k_ba<<<MT_, 256>>>(h, bw, aw, Alog, dtb, beta, eg);
    k_conv<true ><<<dim3(T_, H_,      B_), 256>>>(qlin, qcw, qn, H_);
    k_conv<true ><<<dim3(T_, NH_*H_, B_), 256>>>(klin, kcw, kn, NH_*H_);
    k_conv<false><<<dim3(T_, NH_*H_, B_), 256>>>(vlin, vcw, vn, NH_*H_);

    k_scan<<<B_*H_*8, 256>>>(qn, kn, vn, beta, eg, ob);

    k_onorm<<<MT_*H_, 256>>>(ob, onw, onh, onl);
    hm_gemm<true><<<dim3(D_/BN, MT_/BM), 256>>>(onh, onl, woh, wol, xf, x2, D_, D_);

    // ---- MLP ----
    k_rms2<false><<<MT_, 256>>>(x2, mnw, nullptr, h2h, h2l);
    hm_gemm<false><<<dim3(I_/BN, MT_/BM), 256>>>(h2h, h2l, wgh, wgl, nullptr, gl, D_, I_);
    hm_gemm<false><<<dim3(I_/BN, MT_/BM), 256>>>(h2h, h2l, wuh, wul, nullptr, ul, D_, I_);
    {
        size_t n4 = (size_t)MT_*I_/4;
        k_swiglu_cvt<<<(unsigned)((n4+255)/256), 256>>>(gl, ul, mh, ml, n4);
    }
    hm_gemm<true><<<dim3(D_/BN, MT_/BM), 256>>>(mh, ml, wdh, wdl, x2, out, I_, D_);

    // ---- second output: final hidden state ----
    k_last<<<B_*D_/256, 256>>>(out, out + (size_t)MT_*D_);
}

// round 6
// speedup vs baseline: 1.4107x; 1.0219x over previous
#include <cuda_runtime.h>
#include <cuda_bf16.h>
#include <math.h>
#include <stdint.h>

// Problem constants
#define B_ 8
#define T_ 2048
#define D_ 1024
#define H_ 4
#define DK_ 256
#define DV_ 256
#define NH_ 2
#define KC_ 4
#define I_ 2816
#define EPS_ 1e-6f

#define MT_ (B_*T_)          // 16384 rows

// ---------------- scratch (device globals; no allocation allowed) ----------------
__device__ float g_es[B_*D_];
__device__ float g_ge[B_*D_];
__device__ float g_gx[MT_*D_];
__device__ float g_xf[MT_*D_];
__device__ float g_h [MT_*D_];
__device__ float g_qlin[MT_*D_];
__device__ float g_klin[MT_*2048];
__device__ float g_vlin[MT_*2048];
__device__ float g_qn[MT_*D_];          // [B,H,T,DK]
__device__ float g_kn[MT_*2048];        // [B,NH*H,T,DK]
__device__ float g_vn[MT_*2048];        // [B,NH*H,T,DV]
__device__ float g_beta[B_*NH_*H_*T_];
__device__ float g_eg[B_*H_*T_];
__device__ float g_o [MT_*D_];          // [B,T,H,DV]
__device__ float g_x2[MT_*D_];
__device__ float g_gl[MT_*I_];
__device__ float g_ul[MT_*I_];

// bf16 hi/lo split scratch (activations)
__device__ __nv_bfloat16 g_xh[MT_*D_],  g_xl[MT_*D_];
__device__ __nv_bfloat16 g_hh[MT_*D_],  g_hl[MT_*D_];
__device__ __nv_bfloat16 g_onh[MT_*D_], g_onl[MT_*D_];
__device__ __nv_bfloat16 g_h2h[MT_*D_], g_h2l[MT_*D_];
__device__ __nv_bfloat16 g_mh[MT_*I_],  g_ml[MT_*I_];
// bf16 hi/lo weights
__device__ __nv_bfloat16 g_wsgh[D_*D_],   g_wsgl[D_*D_];
__device__ __nv_bfloat16 g_wqh[D_*D_],    g_wql[D_*D_];
__device__ __nv_bfloat16 g_wkh[2048*D_],  g_wkl[2048*D_];
__device__ __nv_bfloat16 g_wvh[2048*D_],  g_wvl[2048*D_];
__device__ __nv_bfloat16 g_woh[D_*D_],    g_wol[D_*D_];
__device__ __nv_bfloat16 g_wgh[I_*D_],    g_wgl[I_*D_];
__device__ __nv_bfloat16 g_wuh[I_*D_],    g_wul[I_*D_];
__device__ __nv_bfloat16 g_wdh[D_*I_],    g_wdl[D_*I_];

// ---------------- helpers ----------------
__device__ __forceinline__ float sigmoidf_(float x){ return 1.f/(1.f+expf(-x)); }
__device__ __forceinline__ float softplusf_(float x){ return x>20.f? x : log1pf(expf(x)); }

__device__ __forceinline__ float blockReduce256(float v){
    __shared__ float sh[8];
    #pragma unroll
    for(int o=16;o;o>>=1) v += __shfl_xor_sync(0xffffffffu, v, o);
    if((threadIdx.x&31)==0) sh[threadIdx.x>>5] = v;
    __syncthreads();
    float s = 0.f;
    #pragma unroll
    for(int i=0;i<8;i++) s += sh[i];
    return s;
}

__device__ __forceinline__ uint32_t smem_u32(const void* p){
    uint32_t a;
    asm("{ .reg .u64 t; cvta.to.shared.u64 t, %1; cvt.u32.u64 %0, t; }" : "=r"(a) : "l"(p));
    return a;
}
__device__ __forceinline__ void cp16(uint32_t s, const void* g){
    asm volatile("cp.async.cg.shared.global [%0], [%1], 16;" :: "r"(s), "l"(g));
}
__device__ __forceinline__ void cp_commit(){
    asm volatile("cp.async.commit_group;" ::: "memory");
}
template<int N>
__device__ __forceinline__ void cp_wait(){
    asm volatile("cp.async.wait_group %0;" :: "n"(N) : "memory");
}
__device__ __forceinline__ void ldm_x4(uint32_t* r, uint32_t addr){
    asm volatile("ldmatrix.sync.aligned.m8n8.x4.shared.b16 {%0,%1,%2,%3}, [%4];"
        : "=r"(r[0]), "=r"(r[1]), "=r"(r[2]), "=r"(r[3]) : "r"(addr));
}
__device__ __forceinline__ void mma16816(float* d, const uint32_t* a, const uint32_t* b){
    asm volatile("mma.sync.aligned.m16n8k16.row.col.f32.bf16.bf16.f32 "
        "{%0,%1,%2,%3}, {%4,%5,%6,%7}, {%8,%9}, {%0,%1,%2,%3};"
        : "+f"(d[0]), "+f"(d[1]), "+f"(d[2]), "+f"(d[3])
        : "r"(a[0]), "r"(a[1]), "r"(a[2]), "r"(a[3]), "r"(b[0]), "r"(b[1]));
}

// ---------------- HMMA bf16 3-term GEMM ----------------
// C[M,N] = A[M,K]*B[N,K]^T fp32-accurate via bf16 split: ah*bh + al*bh + ah*bl
// CTA tile 128x128, BK=32, 8 warps (4x2), warp tile 32x64, 3-stage cp.async.
#define BM 128
#define BN 128
#define ASTR 40   // bf16 row stride in smem (80B) -> conflict-free ldmatrix
#define STG_BYTES (BM*ASTR*2)        // 10240 per matrix per stage
#define STAGE_BYTES (2*STG_BYTES)    // A + B
#define GSM_BYTES (3*STAGE_BYTES)    // 61440

template<bool RES>
__global__ void __launch_bounds__(256,2)
hm_gemm(const __nv_bfloat16* __restrict__ Ah, const __nv_bfloat16* __restrict__ Al,
        const __nv_bfloat16* __restrict__ Bh, const __nv_bfloat16* __restrict__ Bl,
        const float* __restrict__ Res, float* __restrict__ C, int K, int ldc)
{
    extern __shared__ __align__(16) char smem_raw[];

    int tid = threadIdx.x, wid = tid>>5, lane = tid&31;
    int rowBase = blockIdx.y*BM, colBase = blockIdx.x*BN;
    int wr = wid & 3, wc = wid >> 2;
    int mBase = wr*32, nBase = wc*64;

    int nk = K >> 5;          // K/32 chunks per segment
    int nIter = 3*nk;

    float acc[2][8][4];
    #pragma unroll
    for(int mi=0;mi<2;mi++)
        #pragma unroll
        for(int ni=0;ni<8;ni++)
            #pragma unroll
            for(int q=0;q<4;q++) acc[mi][ni][q]=0.f;

    // loader indices: 512 16B-chunks per matrix, 2 per thread
    int lr = tid >> 2;          // row (0..63; +64 with j)
    int lc = tid & 3;           // 16B-chunk within 32-col row

    uint32_t aS[3][2], bS[3][2];
    #pragma unroll
    for(int s=0;s<3;s++){
        #pragma unroll
        for(int j=0;j<2;j++){
            int r = lr + j*64;
            uint32_t off = (uint32_t)((r*ASTR + lc*8)*2);
            aS[s][j] = smem_u32(smem_raw + s*STAGE_BYTES + off);
            bS[s][j] = smem_u32(smem_raw + s*STAGE_BYTES + STG_BYTES + off);
        }
    }

    auto stage = [&](int it){
        if(it < nIter){
            int buf = it % 3;
            int seg = it / nk, cc = it - seg*nk;
            const __nv_bfloat16* As = (seg==1)? Al : Ah;
            const __nv_bfloat16* Bs = (seg==2)? Bl : Bh;
            int k0 = cc<<5;
            #pragma unroll
            for(int j=0;j<2;j++){
                int r = lr + j*64;
                cp16(aS[buf][j], As + (size_t)(rowBase+r)*K + k0 + lc*8);
                cp16(bS[buf][j], Bs + (size_t)(colBase+r)*K + k0 + lc*8);
            }
        }
        cp_commit();   // uniform group count even when empty
    };

    // prologue: stages 0,1
    stage(0);
    stage(1);

    // precompute ldmatrix smem offsets per stage
    uint32_t aL[3], bL[3];
    {
        int arow = mBase + (lane&15);
        int acol = (lane>>4)<<3;
        int brow = nBase + (lane&7) + (((lane>>4)&1)<<3);
        int bcol = ((lane>>3)&1)<<3;
        #pragma unroll
        for(int s=0;s<3;s++){
            aL[s] = smem_u32(smem_raw + s*STAGE_BYTES + (uint32_t)((arow*ASTR + acol)*2));
            bL[s] = smem_u32(smem_raw + s*STAGE_BYTES + STG_BYTES + (uint32_t)((brow*ASTR + bcol)*2));
        }
    }

    for(int it=0; it<nIter; it++){
        int buf = it % 3;
        cp_wait<1>();          // stage `it` resident (stage it+1 may be pending)
        __syncthreads();       // also guarantees everyone done reading buf from it-1

        #pragma unroll
        for(int ks=0; ks<2; ks++){
            uint32_t af[2][4], bfr[8][2];
            #pragma unroll
            for(int mi=0;mi<2;mi++)
                ldm_x4(af[mi], aL[buf] + (uint32_t)((mi*16*ASTR + ks*16)*2));
            #pragma unroll
            for(int n4=0;n4<4;n4++){
                uint32_t r4[4];
                ldm_x4(r4, bL[buf] + (uint32_t)((n4*16*ASTR + ks*16)*2));
                bfr[n4*2+0][0]=r4[0]; bfr[n4*2+0][1]=r4[1];
                bfr[n4*2+1][0]=r4[2]; bfr[n4*2+1][1]=r4[3];
            }
            #pragma unroll
            for(int mi=0;mi<2;mi++)
                #pragma unroll
                for(int ni=0;ni<8;ni++)
                    mma16816(acc[mi][ni], af[mi], bfr[ni]);
        }

        stage(it+2);           // fill buffer (it+2)%3 == (it-1)%3, safe post-sync
    }

    // epilogue
    int qr = lane>>2, qc = lane&3;
    #pragma unroll
    for(int mi=0;mi<2;mi++){
        #pragma unroll
        for(int ni=0;ni<8;ni++){
            int row0 = rowBase + mBase + mi*16 + qr;
            int col  = colBase + nBase + ni*8 + qc*2;
            float2 v0 = make_float2(acc[mi][ni][0], acc[mi][ni][1]);
            float2 v1 = make_float2(acc[mi][ni][2], acc[mi][ni][3]);
            if(RES){
                float2 r0 = *(const float2*)(Res + (size_t)row0*ldc + col);
                float2 r1 = *(const float2*)(Res + (size_t)(row0+8)*ldc + col);
                v0.x+=r0.x; v0.y+=r0.y; v1.x+=r1.x; v1.y+=r1.y;
            }
            *(float2*)(C + (size_t)row0*ldc + col) = v0;
            *(float2*)(C + (size_t)(row0+8)*ldc + col) = v1;
        }
    }
}

// ---------------- hi/lo conversion (rowwise, strided source) ----------------
__global__ void k_cvt(const float* __restrict__ in, int ld, int cols,
                      __nv_bfloat16* __restrict__ hi, __nv_bfloat16* __restrict__ lo){
    int r = blockIdx.x;
    const float* ip = in + (size_t)r*ld;
    __nv_bfloat16* hp = hi + (size_t)r*cols;
    __nv_bfloat16* lp = lo + (size_t)r*cols;
    for(int c = threadIdx.x*4; c < cols; c += 1024){
        float4 v = *(const float4*)(ip + c);
        __nv_bfloat16 h0=__float2bfloat16(v.x), h1=__float2bfloat16(v.y);
        __nv_bfloat16 h2=__float2bfloat16(v.z), h3=__float2bfloat16(v.w);
        *(__nv_bfloat162*)(hp+c)   = __nv_bfloat162(h0,h1);
        *(__nv_bfloat162*)(hp+c+2) = __nv_bfloat162(h2,h3);
        *(__nv_bfloat162*)(lp+c)   = __nv_bfloat162(
            __float2bfloat16(v.x-__bfloat162float(h0)), __float2bfloat16(v.y-__bfloat162float(h1)));
        *(__nv_bfloat162*)(lp+c+2) = __nv_bfloat162(
            __float2bfloat16(v.z-__bfloat162float(h2)), __float2bfloat16(v.w-__bfloat162float(h3)));
    }
}

// ---------------- small warp-dot kernels ----------------
__global__ void k_es(const float* __restrict__ prev, const float* __restrict__ W,
                     float* __restrict__ es){
    int b = blockIdx.y;
    int w = threadIdx.x>>5, l = threadIdx.x&31;
    int i = blockIdx.x*8 + w;
    const float* pr = prev + b*D_;
    const float* wr = W + (size_t)i*D_;
    float s=0.f;
    for(int j=l;j<D_;j+=32) s += pr[j]*wr[j];
    #pragma unroll
    for(int o=16;o;o>>=1) s += __shfl_xor_sync(0xffffffffu,s,o);
    if(!l) es[b*D_+i]=s;
}

__global__ void k_ge(const float* __restrict__ es, const float* __restrict__ Wg,
                     const float* __restrict__ bias, float* __restrict__ ge){
    int b = blockIdx.y;
    int w = threadIdx.x>>5, l = threadIdx.x&31;
    int i = blockIdx.x*8 + w;
    const float* er = es + b*D_;
    const float* wr = Wg + (size_t)i*(2*D_) + D_;
    float s=0.f;
    for(int j=l;j<D_;j+=32) s += er[j]*wr[j];
    #pragma unroll
    for(int o=16;o;o>>=1) s += __shfl_xor_sync(0xffffffffu,s,o);
    if(!l) ge[b*D_+i] = s + bias[i];
}

// ---------------- elementwise fusion ----------------
__global__ void k_fuse(const float* __restrict__ x, const float* __restrict__ gx,
                       const float* __restrict__ ge, const float* __restrict__ es,
                       float* __restrict__ xf){
    size_t idx = (size_t)blockIdx.x*256 + threadIdx.x;
    int i = (int)(idx & (D_-1));
    int m = (int)(idx >> 10);
    int b = m >> 11;
    float g = sigmoidf_(gx[idx] + ge[b*D_+i]);
    float e = es[b*D_+i];
    xf[idx] = g*x[idx] + (1.f-g)*e;
}

// RMSNorm over D=1024: optional fp32 out + hi/lo bf16 out
template<bool F32OUT>
__global__ void k_rms2(const float* __restrict__ in, const float* __restrict__ w,
                       float* __restrict__ out,
                       __nv_bfloat16* __restrict__ hi, __nv_bfloat16* __restrict__ lo){
    int row = blockIdx.x, tid = threadIdx.x;
    const float4* ir = (const float4*)(in + (size_t)row*D_);
    float4 v = ir[tid];
    float ss = blockReduce256(v.x*v.x+v.y*v.y+v.z*v.z+v.w*v.w);
    float sc = rsqrtf(ss*(1.f/D_) + EPS_);
    float4 ww = ((const float4*)w)[tid];
    float4 y = make_float4(v.x*sc*ww.x, v.y*sc*ww.y, v.z*sc*ww.z, v.w*sc*ww.w);
    if(F32OUT) ((float4*)(out + (size_t)row*D_))[tid] = y;
    int c = tid*4;
    __nv_bfloat16* hp = hi + (size_t)row*D_;
    __nv_bfloat16* lp = lo + (size_t)row*D_;
    __nv_bfloat16 h0=__float2bfloat16(y.x), h1=__float2bfloat16(y.y);
    __nv_bfloat16 h2=__float2bfloat16(y.z), h3=__float2bfloat16(y.w);
    *(__nv_bfloat162*)(hp+c)   = __nv_bfloat162(h0,h1);
    *(__nv_bfloat162*)(hp+c+2) = __nv_bfloat162(h2,h3);
    *(__nv_bfloat162*)(lp+c)   = __nv_bfloat162(
        __float2bfloat16(y.x-__bfloat162float(h0)), __float2bfloat16(y.y-__bfloat162float(h1)));
    *(__nv_bfloat162*)(lp+c+2) = __nv_bfloat162(
        __float2bfloat16(y.z-__bfloat162float(h2)), __float2bfloat16(y.w-__bfloat162float(h3)));
}

// beta + decay gate from h
__global__ void k_ba(const float* __restrict__ h, const float* __restrict__ bw,
                     const float* __restrict__ aw, const float* __restrict__ A_log,
                     const float* __restrict__ dtb,
                     float* __restrict__ beta, float* __restrict__ eg){
    int row = blockIdx.x;
    int b = row >> 11, t = row & (T_-1);
    int w = threadIdx.x>>5, l = threadIdx.x&31;
    const float* hr = h + (size_t)row*D_;
    {
        const float* wr = bw + (size_t)w*D_;
        float s=0.f;
        for(int j=l;j<D_;j+=32) s += hr[j]*wr[j];
        #pragma unroll
        for(int o=16;o;o>>=1) s += __shfl_xor_sync(0xffffffffu,s,o);
        if(!l){
            int i = w>>2, hh = w&3;
            beta[(( (b*NH_+i)*H_+hh )*T_) + t] = 2.f*sigmoidf_(s);
        }
    }
    if(w < H_){
        const float* ar = aw + (size_t)w*D_;
        float s=0.f;
        for(int j=l;j<D_;j+=32) s += hr[j]*ar[j];
        #pragma unroll
        for(int o=16;o;o>>=1) s += __shfl_xor_sync(0xffffffffu,s,o);
        if(!l){
            float g = -expf(A_log[w]) * softplusf_(s + dtb[w]);
            eg[(b*H_+w)*T_ + t] = expf(g);
        }
    }
}

// causal depthwise conv (K=4) + silu (+ optional L2 norm per head) + relayout
template<bool NORM>
__global__ void k_conv(const float* __restrict__ in, const float* __restrict__ cw,
                       float* __restrict__ out, int nheads){
    int t = blockIdx.x, hd = blockIdx.y, b = blockIdx.z, c = threadIdx.x;
    int C = nheads*256;
    int ch = hd*256 + c;
    const float* wp = cw + (size_t)ch*KC_;
    float acc = 0.f;
    #pragma unroll
    for(int j=0;j<KC_;j++){
        int tt = t - (KC_-1) + j;
        if(tt>=0) acc += in[((size_t)(b*T_+tt))*C + ch]*wp[j];
    }
    float s = acc * sigmoidf_(acc);
    float y;
    if(NORM){
        float ss = blockReduce256(s*s);
        y = s * rsqrtf(ss + EPS_);
    } else y = s;
    out[(((size_t)(b*nheads+hd)*T_)+t)*256 + c] = y;
}

// ---------------- gated delta-product scan ----------------
__global__ void __launch_bounds__(256) k_scan(
    const float* __restrict__ qn, const float* __restrict__ kn,
    const float* __restrict__ vn, const float* __restrict__ beta,
    const float* __restrict__ eg, float* __restrict__ o){
    int cta = blockIdx.x;
    int ch = cta & 7;
    int hh = (cta>>3)&3;
    int b  = cta>>5;
    int vbase = ch*32;
    int tid = threadIdx.x;
    int w = tid>>5, l = tid&31;
    int col = w*4 + (l>>3);
    int kseg = l&7;
    int k0i = kseg*32;

    __shared__ float sq[2][256], sk0[2][256], sk1[2][256];
    __shared__ float sv0[2][32], sv1[2][32], ssc[2][4];

    float S[32];
    #pragma unroll
    for(int j=0;j<32;j++) S[j]=0.f;

    const float* qrow  = qn + (size_t)(b*H_+hh)*T_*256;
    const float* k0row = kn + (size_t)(b*8 + hh)*T_*256;
    const float* k1row = kn + (size_t)(b*8 + H_ + hh)*T_*256;
    const float* v0row = vn + (size_t)(b*8 + hh)*T_*256 + vbase;
    const float* v1row = vn + (size_t)(b*8 + H_ + hh)*T_*256 + vbase;
    const float* b0p = beta + ((b*NH_+0)*H_+hh)*T_;
    const float* b1p = beta + ((b*NH_+1)*H_+hh)*T_;
    const float* egp = eg + (b*H_+hh)*T_;

    sq [0][tid] = qrow[tid];
    sk0[0][tid] = k0row[tid];
    sk1[0][tid] = k1row[tid];
    if(tid<32) sv0[0][tid] = v0row[tid];
    else if(tid<64) sv1[0][tid-32] = v1row[tid-32];
    if(tid==64) ssc[0][0]=b0p[0];
    if(tid==65) ssc[0][1]=b1p[0];
    if(tid==66) ssc[0][2]=egp[0];
    __syncthreads();

    const float out_scale = rsqrtf((float)DK_);

    for(int t=0;t<T_;t++){
        int cb = t&1, nb = cb^1;
        bool hn = (t+1 < T_);
        float pq=0.f, pk0=0.f, pk1=0.f, pv=0.f, psc=0.f;
        if(hn){
            size_t off = (size_t)(t+1)*256;
            pq  = qrow [off+tid];
            pk0 = k0row[off+tid];
            pk1 = k1row[off+tid];
            if(tid<32) pv = v0row[off+tid];
            else if(tid<64) pv = v1row[off + tid-32];
            if(tid==64) psc = b0p[t+1];
            if(tid==65) psc = b1p[t+1];
            if(tid==66) psc = egp[t+1];
        }

        float egv = ssc[cb][2];
        float b0v = ssc[cb][0], b1v = ssc[cb][1];
        float v0c = sv0[cb][col], v1c = sv1[cb][col];

        #pragma unroll
        for(int j=0;j<32;j++) S[j] *= egv;

        float kr[32];
        {
            const float4* kp = (const float4*)(&sk0[cb][k0i]);
            #pragma unroll
            for(int j=0;j<8;j++){ float4 k4 = kp[j];
                kr[j*4+0]=k4.x; kr[j*4+1]=k4.y; kr[j*4+2]=k4.z; kr[j*4+3]=k4.w; }
            float pred=0.f;
            #pragma unroll
            for(int j=0;j<32;j++) pred += S[j]*kr[j];
            pred += __shfl_xor_sync(0xffffffffu,pred,1);
            pred += __shfl_xor_sync(0xffffffffu,pred,2);
            pred += __shfl_xor_sync(0xffffffffu,pred,4);
            float u = (v0c - pred)*b0v;
            #pragma unroll
            for(int j=0;j<32;j++) S[j] += kr[j]*u;
        }
        {
            const float4* kp = (const float4*)(&sk1[cb][k0i]);
            #pragma unroll
            for(int j=0;j<8;j++){ float4 k4 = kp[j];
                kr[j*4+0]=k4.x; kr[j*4+1]=k4.y; kr[j*4+2]=k4.z; kr[j*4+3]=k4.w; }
            float pred=0.f;
            #pragma unroll
            for(int j=0;j<32;j++) pred += S[j]*kr[j];
            pred += __shfl_xor_sync(0xffffffffu,pred,1);
            pred += __shfl_xor_sync(0xffffffffu,pred,2);
            pred += __shfl_xor_sync(0xffffffffu,pred,4);
            float u = (v1c - pred)*b1v;
            #pragma unroll
            for(int j=0;j<32;j++) S[j] += kr[j]*u;
        }
        {
            const float4* qp = (const float4*)(&sq[cb][k0i]);
            float po=0.f;
            #pragma unroll
            for(int j=0;j<8;j++){ float4 q4 = qp[j];
                po += S[j*4+0]*q4.x + S[j*4+1]*q4.y + S[j*4+2]*q4.z + S[j*4+3]*q4.w; }
            po += __shfl_xor_sync(0xffffffffu,po,1);
            po += __shfl_xor_sync(0xffffffffu,po,2);
            po += __shfl_xor_sync(0xffffffffu,po,4);
            if(kseg==0)
                o[(((size_t)(b*T_+t))*H_ + hh)*256 + vbase + col] = po*out_scale;
        }

        if(hn){
            sq [nb][tid]=pq; sk0[nb][tid]=pk0; sk1[nb][tid]=pk1;
            if(tid<32) sv0[nb][tid]=pv;
            else if(tid<64) sv1[nb][tid-32]=pv;
            if(tid==64) ssc[nb][0]=psc;
            if(tid==65) ssc[nb][1]=psc;
            if(tid==66) ssc[nb][2]=psc;
        }
        __syncthreads();
    }
}

// per-head RMSNorm over DV=256 -> hi/lo bf16
__global__ void k_onorm(const float* __restrict__ o, const float* __restrict__ w,
                        __nv_bfloat16* __restrict__ hi, __nv_bfloat16* __restrict__ lo){
    int row = blockIdx.x, tid = threadIdx.x;
    float v = o[(size_t)row*256 + tid];
    float ss = blockReduce256(v*v);
    float y = v * rsqrtf(ss*(1.f/256.f) + EPS_) * w[tid];
    __nv_bfloat16 h = __float2bfloat16(y);
    hi[(size_t)row*256 + tid] = h;
    lo[(size_t)row*256 + tid] = __float2bfloat16(y - __bfloat162float(h));
}

__global__ void k_swiglu_cvt(const float* __restrict__ gl, const float* __restrict__ ul,
                             __nv_bfloat16* __restrict__ mh, __nv_bfloat16* __restrict__ ml,
                             size_t n4){
    size_t i4 = (size_t)blockIdx.x*256 + threadIdx.x;
    if(i4 < n4){
        size_t c = i4*4;
        float4 g4 = *(const float4*)(gl + c);
        float4 u4 = *(const float4*)(ul + c);
        float m0 = g4.x*sigmoidf_(g4.x)*u4.x;
        float m1 = g4.y*sigmoidf_(g4.y)*u4.y;
        float m2 = g4.z*sigmoidf_(g4.z)*u4.z;
        float m3 = g4.w*sigmoidf_(g4.w)*u4.w;
        __nv_bfloat16 h0=__float2bfloat16(m0), h1=__float2bfloat16(m1);
        __nv_bfloat16 h2=__float2bfloat16(m2), h3=__float2bfloat16(m3);
        *(__nv_bfloat162*)(mh+c)   = __nv_bfloat162(h0,h1);
        *(__nv_bfloat162*)(mh+c+2) = __nv_bfloat162(h2,h3);
        *(__nv_bfloat162*)(ml+c)   = __nv_bfloat162(
            __float2bfloat16(m0-__bfloat162float(h0)), __float2bfloat16(m1-__bfloat162float(h1)));
        *(__nv_bfloat162*)(ml+c+2) = __nv_bfloat162(
            __float2bfloat16(m2-__bfloat162float(h2)), __float2bfloat16(m3-__bfloat162float(h3)));
    }
}

__global__ void k_last(const float* __restrict__ out, float* __restrict__ dst){
    int idx = blockIdx.x*256 + threadIdx.x; // B*D = 8192
    int b = idx >> 10, i = idx & (D_-1);
    dst[idx] = out[((size_t)(b*T_ + (T_-1)))*D_ + i];
}

// ---------------- launcher ----------------
extern "C" void kernel_launch(void* const* d_in, const int* in_sizes, int n_in,
                              void* d_out, int out_size){
    const float* x    = (const float*)d_in[0];
    const float* prev = (const float*)d_in[1];
    const float* spw  = (const float*)d_in[2];
    const float* sgw  = (const float*)d_in[3];
    const float* sgb  = (const float*)d_in[4];
    const float* anw  = (const float*)d_in[5];
    const float* qw   = (const float*)d_in[6];
    const float* kw   = (const float*)d_in[7];
    const float* vw   = (const float*)d_in[8];
    const float* bw   = (const float*)d_in[9];
    const float* aw   = (const float*)d_in[10];
    const float* Alog = (const float*)d_in[11];
    const float* dtb  = (const float*)d_in[12];
    const float* qcw  = (const float*)d_in[13];
    const float* kcw  = (const float*)d_in[14];
    const float* vcw  = (const float*)d_in[15];
    const float* onw  = (const float*)d_in[16];
    const float* ow   = (const float*)d_in[17];
    const float* mnw  = (const float*)d_in[18];
    const float* gw   = (const float*)d_in[19];
    const float* uw   = (const float*)d_in[20];
    const float* dw   = (const float*)d_in[21];
    float* out = (float*)d_out;

    float *es,*ge,*gx,*xf,*h,*qlin,*klin,*vlin,*qn,*kn,*vn,*beta,*eg,*ob,*x2,*gl,*ul;
    cudaGetSymbolAddress((void**)&es, g_es);
    cudaGetSymbolAddress((void**)&ge, g_ge);
    cudaGetSymbolAddress((void**)&gx, g_gx);
    cudaGetSymbolAddress((void**)&xf, g_xf);
    cudaGetSymbolAddress((void**)&h,  g_h);
    cudaGetSymbolAddress((void**)&qlin, g_qlin);
    cudaGetSymbolAddress((void**)&klin, g_klin);
    cudaGetSymbolAddress((void**)&vlin, g_vlin);
    cudaGetSymbolAddress((void**)&qn, g_qn);
    cudaGetSymbolAddress((void**)&kn, g_kn);
    cudaGetSymbolAddress((void**)&vn, g_vn);
    cudaGetSymbolAddress((void**)&beta, g_beta);
    cudaGetSymbolAddress((void**)&eg, g_eg);
    cudaGetSymbolAddress((void**)&ob, g_o);
    cudaGetSymbolAddress((void**)&x2, g_x2);
    cudaGetSymbolAddress((void**)&gl, g_gl);
    cudaGetSymbolAddress((void**)&ul, g_ul);

    __nv_bfloat16 *xh,*xl,*hh,*hl,*onh,*onl,*h2h,*h2l,*mh,*ml;
    __nv_bfloat16 *wsgh,*wsgl,*wqh,*wql,*wkh,*wkl,*wvh,*wvl,*woh,*wol,*wgh,*wgl,*wuh,*wul,*wdh,*wdl;
    cudaGetSymbolAddress((void**)&xh, g_xh);   cudaGetSymbolAddress((void**)&xl, g_xl);
    cudaGetSymbolAddress((void**)&hh, g_hh);   cudaGetSymbolAddress((void**)&hl, g_hl);
    cudaGetSymbolAddress((void**)&onh, g_onh); cudaGetSymbolAddress((void**)&onl, g_onl);
    cudaGetSymbolAddress((void**)&h2h, g_h2h); cudaGetSymbolAddress((void**)&h2l, g_h2l);
    cudaGetSymbolAddress((void**)&mh, g_mh);   cudaGetSymbolAddress((void**)&ml, g_ml);
    cudaGetSymbolAddress((void**)&wsgh, g_wsgh); cudaGetSymbolAddress((void**)&wsgl, g_wsgl);
    cudaGetSymbolAddress((void**)&wqh, g_wqh);   cudaGetSymbolAddress((void**)&wql, g_wql);
    cudaGetSymbolAddress((void**)&wkh, g_wkh);   cudaGetSymbolAddress((void**)&wkl, g_wkl);
    cudaGetSymbolAddress((void**)&wvh, g_wvh);   cudaGetSymbolAddress((void**)&wvl, g_wvl);
    cudaGetSymbolAddress((void**)&woh, g_woh);   cudaGetSymbolAddress((void**)&wol, g_wol);
    cudaGetSymbolAddress((void**)&wgh, g_wgh);   cudaGetSymbolAddress((void**)&wgl, g_wgl);
    cudaGetSymbolAddress((void**)&wuh, g_wuh);   cudaGetSymbolAddress((void**)&wul, g_wul);
    cudaGetSymbolAddress((void**)&wdh, g_wdh);   cudaGetSymbolAddress((void**)&wdl, g_wdl);

    cudaFuncSetAttribute(hm_gemm<false>, cudaFuncAttributeMaxDynamicSharedMemorySize, GSM_BYTES);
    cudaFuncSetAttribute(hm_gemm<true>,  cudaFuncAttributeMaxDynamicSharedMemorySize, GSM_BYTES);

    // ---- launches 0-4 (so launch #5 = first hm_gemm for ncu -s 5 -c 1) ----
    k_cvt<<<1024, 256>>>(sgw, 2*D_, D_, wsgh, wsgl);   // 0
    k_cvt<<<MT_, 256>>>(x, D_, D_, xh, xl);            // 1
    k_es<<<dim3(D_/8, B_), 256>>>(prev, spw, es);      // 2
    k_ge<<<dim3(D_/8, B_), 256>>>(es, sgw, sgb, ge);   // 3
    k_cvt<<<1024, 256>>>(qw, D_, D_, wqh, wql);        // 4

    // ---- state fusion gate GEMM (launch 5, gets profiled) ----
    hm_gemm<false><<<dim3(D_/BN, MT_/BM), 256, GSM_BYTES>>>(xh, xl, wsgh, wsgl, nullptr, gx, D_, D_);
    k_fuse<<<MT_*D_/256, 256>>>(x, gx, ge, es, xf);

    // ---- remaining weight conversions ----
    k_cvt<<<2048, 256>>>(kw, D_, D_, wkh, wkl);
    k_cvt<<<2048, 256>>>(vw, D_, D_, wvh, wvl);
    k_cvt<<<1024, 256>>>(ow, D_, D_, woh, wol);
    k_cvt<<<I_, 256>>>(gw, D_, D_, wgh, wgl);
    k_cvt<<<I_, 256>>>(uw, D_, D_, wuh, wul);
    k_cvt<<<1024, 256>>>(dw, I_, I_, wdh, wdl);

    // ---- attention sub-block ----
    k_rms2<true><<<MT_, 256>>>(xf, anw, h, hh, hl);
    hm_gemm<false><<<dim3(D_/BN, MT_/BM), 256, GSM_BYTES>>>(hh, hl, wqh, wql, nullptr, qlin, D_, D_);
    hm_gemm<false><<<dim3(2048/BN, MT_/BM), 256, GSM_BYTES>>>(hh, hl, wkh, wkl, nullptr, klin, D_, 2048);
    hm_gemm<false><<<dim3(2048/BN, MT_/BM), 256, GSM_BYTES>>>(hh, hl, wvh, wvl, nullptr, vlin, D_, 2048);
    k_ba<<<MT_, 256>>>(h, bw, aw, Alog, dtb, beta, eg);
    k_conv<true ><<<dim3(T_, H_,      B_), 256>>>(qlin, qcw, qn, H_);
    k_conv<true ><<<dim3(T_, NH_*H_, B_), 256>>>(klin, kcw, kn, NH_*H_);
    k_conv<false><<<dim3(T_, NH_*H_, B_), 256>>>(vlin, vcw, vn, NH_*H_);

    k_scan<<<B_*H_*8, 256>>>(qn, kn, vn, beta, eg, ob);

    k_onorm<<<MT_*H_, 256>>>(ob, onw, onh, onl);
    hm_gemm<true><<<dim3(D_/BN, MT_/BM), 256, GSM_BYTES>>>(onh, onl, woh, wol, xf, x2, D_, D_);

    // ---- MLP ----
    k_rms2<false><<<MT_, 256>>>(x2, mnw, nullptr, h2h, h2l);
    hm_gemm<false><<<dim3(I_/BN, MT_/BM), 256, GSM_BYTES>>>(h2h, h2l, wgh, wgl, nullptr, gl, D_, I_);
    hm_gemm<false><<<dim3(I_/BN, MT_/BM), 256, GSM_BYTES>>>(h2h, h2l, wuh, wul, nullptr, ul, D_, I_);
    {
        size_t n4 = (size_t)MT_*I_/4;
        k_swiglu_cvt<<<(unsigned)((n4+255)/256), 256>>>(gl, ul, mh, ml, n4);
    }
    hm_gemm<true><<<dim3(D_/BN, MT_/BM), 256, GSM_BYTES>>>(mh, ml, wdh, wdl, x2, out, I_, D_);

    // ---- second output: final hidden state ----
    k_last<<<B_*D_/256, 256>>>(out, out + (size_t)MT_*D_);
}

// round 9
// speedup vs baseline: 1.5335x; 1.0870x over previous
#include <cuda_runtime.h>
#include <cuda_fp16.h>
#include <math.h>
#include <stdint.h>

// Problem constants
#define B_ 8
#define T_ 2048
#define D_ 1024
#define H_ 4
#define DK_ 256
#define DV_ 256
#define NH_ 2
#define KC_ 4
#define I_ 2816
#define EPS_ 1e-6f

#define MT_ (B_*T_)          // 16384 rows

// ---------------- scratch (device globals; no allocation allowed) ----------------
__device__ float g_es[B_*D_];
__device__ float g_ge[B_*D_];
__device__ float g_gx[MT_*D_];
__device__ float g_xf[MT_*D_];
__device__ float g_h [MT_*D_];
__device__ float g_qlin[MT_*D_];
__device__ float g_klin[MT_*2048];
__device__ float g_vlin[MT_*2048];
__device__ float g_qn[MT_*D_];          // [B,H,T,DK]
__device__ float g_kn[MT_*2048];        // [B,NH*H,T,DK]
__device__ float g_vn[MT_*2048];        // [B,NH*H,T,DV]
__device__ float g_beta[B_*NH_*H_*T_];
__device__ float g_eg[B_*H_*T_];
__device__ float g_o [MT_*D_];          // [B,T,H,DV]
__device__ float g_x2[MT_*D_];
__device__ float g_gl[MT_*I_];
__device__ float g_ul[MT_*I_];

// fp16 hi/lo split scratch (activations)
__device__ __half g_xh[MT_*D_],  g_xl[MT_*D_];
__device__ __half g_hh[MT_*D_],  g_hl[MT_*D_];
__device__ __half g_onh[MT_*D_], g_onl[MT_*D_];
__device__ __half g_h2h[MT_*D_], g_h2l[MT_*D_];
__device__ __half g_mh[MT_*I_],  g_ml[MT_*I_];
// fp16 weights (hi only used by GEMM)
__device__ __half g_wsgh[D_*D_];
__device__ __half g_wqh[D_*D_];
__device__ __half g_wkh[2048*D_];
__device__ __half g_wvh[2048*D_];
__device__ __half g_woh[D_*D_];
__device__ __half g_wgh[I_*D_];
__device__ __half g_wuh[I_*D_];
__device__ __half g_wdh[D_*I_];

// ---------------- helpers ----------------
__device__ __forceinline__ float sigmoidf_(float x){ return 1.f/(1.f+expf(-x)); }
__device__ __forceinline__ float softplusf_(float x){ return x>20.f? x : log1pf(expf(x)); }

__device__ __forceinline__ float blockReduce256(float v){
    __shared__ float sh[8];
    #pragma unroll
    for(int o=16;o;o>>=1) v += __shfl_xor_sync(0xffffffffu, v, o);
    if((threadIdx.x&31)==0) sh[threadIdx.x>>5] = v;
    __syncthreads();
    float s = 0.f;
    #pragma unroll
    for(int i=0;i<8;i++) s += sh[i];
    return s;
}

__device__ __forceinline__ uint32_t smem_u32(const void* p){
    uint32_t a;
    asm("{ .reg .u64 t; cvta.to.shared.u64 t, %1; cvt.u32.u64 %0, t; }" : "=r"(a) : "l"(p));
    return a;
}
__device__ __forceinline__ void cp16(uint32_t s, const void* g){
    asm volatile("cp.async.cg.shared.global [%0], [%1], 16;" :: "r"(s), "l"(g));
}
__device__ __forceinline__ void cp_commit(){
    asm volatile("cp.async.commit_group;" ::: "memory");
}
template<int N>
__device__ __forceinline__ void cp_wait(){
    asm volatile("cp.async.wait_group %0;" :: "n"(N) : "memory");
}
__device__ __forceinline__ void ldm_x4(uint32_t* r, uint32_t addr){
    asm volatile("ldmatrix.sync.aligned.m8n8.x4.shared.b16 {%0,%1,%2,%3}, [%4];"
        : "=r"(r[0]), "=r"(r[1]), "=r"(r[2]), "=r"(r[3]) : "r"(addr));
}
__device__ __forceinline__ void mma16816(float* d, const uint32_t* a, const uint32_t* b){
    asm volatile("mma.sync.aligned.m16n8k16.row.col.f32.f16.f16.f32 "
        "{%0,%1,%2,%3}, {%4,%5,%6,%7}, {%8,%9}, {%0,%1,%2,%3};"
        : "+f"(d[0]), "+f"(d[1]), "+f"(d[2]), "+f"(d[3])
        : "r"(a[0]), "r"(a[1]), "r"(a[2]), "r"(a[3]), "r"(b[0]), "r"(b[1]));
}

// ---------------- HMMA fp16 2-term GEMM ----------------
// C[M,N] = A[M,K]*B[N,K]^T ~fp32 via fp16 split: ah*bh + al*bh
// (drops a*bl, rel err ~2^-12). CTA 128x128, BK=32, 8 warps, 3-stage cp.async.
#define BM 128
#define BN 128
#define ASTR 40   // fp16 row stride in smem (80B) -> conflict-free ldmatrix
#define STG_BYTES (BM*ASTR*2)        // 10240 per matrix per stage
#define STAGE_BYTES (2*STG_BYTES)    // A + B
#define GSM_BYTES (3*STAGE_BYTES)    // 61440

template<bool RES>
__global__ void __launch_bounds__(256,2)
hm_gemm(const __half* __restrict__ Ah, const __half* __restrict__ Al,
        const __half* __restrict__ Bh,
        const float* __restrict__ Res, float* __restrict__ C, int K, int ldc)
{
    extern __shared__ __align__(16) char smem_raw[];

    int tid = threadIdx.x, wid = tid>>5, lane = tid&31;
    int rowBase = blockIdx.y*BM, colBase = blockIdx.x*BN;
    int wr = wid & 3, wc = wid >> 2;
    int mBase = wr*32, nBase = wc*64;

    int nk = K >> 5;          // K/32 chunks per segment
    int nIter = 2*nk;

    float acc[2][8][4];
    #pragma unroll
    for(int mi=0;mi<2;mi++)
        #pragma unroll
        for(int ni=0;ni<8;ni++)
            #pragma unroll
            for(int q=0;q<4;q++) acc[mi][ni][q]=0.f;

    // loader indices: 512 16B-chunks per matrix, 2 per thread
    int lr = tid >> 2;          // row (0..63; +64 with j)
    int lc = tid & 3;           // 16B-chunk within 32-col row

    uint32_t aS[3][2], bS[3][2];
    #pragma unroll
    for(int s=0;s<3;s++){
        #pragma unroll
        for(int j=0;j<2;j++){
            int r = lr + j*64;
            uint32_t off = (uint32_t)((r*ASTR + lc*8)*2);
            aS[s][j] = smem_u32(smem_raw + s*STAGE_BYTES + off);
            bS[s][j] = smem_u32(smem_raw + s*STAGE_BYTES + STG_BYTES + off);
        }
    }

    auto stage = [&](int it){
        if(it < nIter){
            int buf = it % 3;
            int seg = it / nk, cc = it - seg*nk;
            const __half* As = seg ? Al : Ah;
            int k0 = cc<<5;
            #pragma unroll
            for(int j=0;j<2;j++){
                int r = lr + j*64;
                cp16(aS[buf][j], As + (size_t)(rowBase+r)*K + k0 + lc*8);
                cp16(bS[buf][j], Bh + (size_t)(colBase+r)*K + k0 + lc*8);
            }
        }
        cp_commit();   // uniform group count even when empty
    };

    // prologue: stages 0,1
    stage(0);
    stage(1);

    // precompute ldmatrix smem offsets per stage
    uint32_t aL[3], bL[3];
    {
        int arow = mBase + (lane&15);
        int acol = (lane>>4)<<3;
        int brow = nBase + (lane&7) + (((lane>>4)&1)<<3);
        int bcol = ((lane>>3)&1)<<3;
        #pragma unroll
        for(int s=0;s<3;s++){
            aL[s] = smem_u32(smem_raw + s*STAGE_BYTES + (uint32_t)((arow*ASTR + acol)*2));
            bL[s] = smem_u32(smem_raw + s*STAGE_BYTES + STG_BYTES + (uint32_t)((brow*ASTR + bcol)*2));
        }
    }

    for(int it=0; it<nIter; it++){
        int buf = it % 3;
        cp_wait<1>();          // stage `it` resident
        __syncthreads();

        #pragma unroll
        for(int ks=0; ks<2; ks++){
            uint32_t af[2][4], bfr[8][2];
            #pragma unroll
            for(int mi=0;mi<2;mi++)
                ldm_x4(af[mi], aL[buf] + (uint32_t)((mi*16*ASTR + ks*16)*2));
            #pragma unroll
            for(int n4=0;n4<4;n4++){
                uint32_t r4[4];
                ldm_x4(r4, bL[buf] + (uint32_t)((n4*16*ASTR + ks*16)*2));
                bfr[n4*2+0][0]=r4[0]; bfr[n4*2+0][1]=r4[1];
                bfr[n4*2+1][0]=r4[2]; bfr[n4*2+1][1]=r4[3];
            }
            #pragma unroll
            for(int mi=0;mi<2;mi++)
                #pragma unroll
                for(int ni=0;ni<8;ni++)
                    mma16816(acc[mi][ni], af[mi], bfr[ni]);
        }

        stage(it+2);
    }

    // epilogue
    int qr = lane>>2, qc = lane&3;
    #pragma unroll
    for(int mi=0;mi<2;mi++){
        #pragma unroll
        for(int ni=0;ni<8;ni++){
            int row0 = rowBase + mBase + mi*16 + qr;
            int col  = colBase + nBase + ni*8 + qc*2;
            float2 v0 = make_float2(acc[mi][ni][0], acc[mi][ni][1]);
            float2 v1 = make_float2(acc[mi][ni][2], acc[mi][ni][3]);
            if(RES){
                float2 r0 = *(const float2*)(Res + (size_t)row0*ldc + col);
                float2 r1 = *(const float2*)(Res + (size_t)(row0+8)*ldc + col);
                v0.x+=r0.x; v0.y+=r0.y; v1.x+=r1.x; v1.y+=r1.y;
            }
            *(float2*)(C + (size_t)row0*ldc + col) = v0;
            *(float2*)(C + (size_t)(row0+8)*ldc + col) = v1;
        }
    }
}

// ---------------- hi/lo conversion ----------------
__global__ void k_cvt2(const float* __restrict__ in, int ld, int cols,
                       __half* __restrict__ hi, __half* __restrict__ lo){
    int r = blockIdx.x;
    const float* ip = in + (size_t)r*ld;
    __half* hp = hi + (size_t)r*cols;
    __half* lp = lo + (size_t)r*cols;
    for(int c = threadIdx.x*4; c < cols; c += 1024){
        float4 v = *(const float4*)(ip + c);
        __half h0=__float2half(v.x), h1=__float2half(v.y);
        __half h2=__float2half(v.z), h3=__float2half(v.w);
        *(__half2*)(hp+c)   = __halves2half2(h0,h1);
        *(__half2*)(hp+c+2) = __halves2half2(h2,h3);
        *(__half2*)(lp+c)   = __halves2half2(
            __float2half(v.x-__half2float(h0)), __float2half(v.y-__half2float(h1)));
        *(__half2*)(lp+c+2) = __halves2half2(
            __float2half(v.z-__half2float(h2)), __float2half(v.w-__half2float(h3)));
    }
}

// weights: hi only
__global__ void k_cvtw(const float* __restrict__ in, int ld, int cols,
                       __half* __restrict__ hi){
    int r = blockIdx.x;
    const float* ip = in + (size_t)r*ld;
    __half* hp = hi + (size_t)r*cols;
    for(int c = threadIdx.x*4; c < cols; c += 1024){
        float4 v = *(const float4*)(ip + c);
        *(__half2*)(hp+c)   = __halves2half2(__float2half(v.x), __float2half(v.y));
        *(__half2*)(hp+c+2) = __halves2half2(__float2half(v.z), __float2half(v.w));
    }
}

// ---------------- small warp-dot kernels ----------------
__global__ void k_es(const float* __restrict__ prev, const float* __restrict__ W,
                     float* __restrict__ es){
    int b = blockIdx.y;
    int w = threadIdx.x>>5, l = threadIdx.x&31;
    int i = blockIdx.x*8 + w;
    const float* pr = prev + b*D_;
    const float* wr = W + (size_t)i*D_;
    float s=0.f;
    for(int j=l;j<D_;j+=32) s += pr[j]*wr[j];
    #pragma unroll
    for(int o=16;o;o>>=1) s += __shfl_xor_sync(0xffffffffu,s,o);
    if(!l) es[b*D_+i]=s;
}

__global__ void k_ge(const float* __restrict__ es, const float* __restrict__ Wg,
                     const float* __restrict__ bias, float* __restrict__ ge){
    int b = blockIdx.y;
    int w = threadIdx.x>>5, l = threadIdx.x&31;
    int i = blockIdx.x*8 + w;
    const float* er = es + b*D_;
    const float* wr = Wg + (size_t)i*(2*D_) + D_;
    float s=0.f;
    for(int j=l;j<D_;j+=32) s += er[j]*wr[j];
    #pragma unroll
    for(int o=16;o;o>>=1) s += __shfl_xor_sync(0xffffffffu,s,o);
    if(!l) ge[b*D_+i] = s + bias[i];
}

// ---------------- elementwise fusion ----------------
__global__ void k_fuse(const float* __restrict__ x, const float* __restrict__ gx,
                       const float* __restrict__ ge, const float* __restrict__ es,
                       float* __restrict__ xf){
    size_t idx = (size_t)blockIdx.x*256 + threadIdx.x;
    int i = (int)(idx & (D_-1));
    int m = (int)(idx >> 10);
    int b = m >> 11;
    float g = sigmoidf_(gx[idx] + ge[b*D_+i]);
    float e = es[b*D_+i];
    xf[idx] = g*x[idx] + (1.f-g)*e;
}

// RMSNorm over D=1024: optional fp32 out + hi/lo fp16 out
template<bool F32OUT>
__global__ void k_rms2(const float* __restrict__ in, const float* __restrict__ w,
                       float* __restrict__ out,
                       __half* __restrict__ hi, __half* __restrict__ lo){
    int row = blockIdx.x, tid = threadIdx.x;
    const float4* ir = (const float4*)(in + (size_t)row*D_);
    float4 v = ir[tid];
    float ss = blockReduce256(v.x*v.x+v.y*v.y+v.z*v.z+v.w*v.w);
    float sc = rsqrtf(ss*(1.f/D_) + EPS_);
    float4 ww = ((const float4*)w)[tid];
    float4 y = make_float4(v.x*sc*ww.x, v.y*sc*ww.y, v.z*sc*ww.z, v.w*sc*ww.w);
    if(F32OUT) ((float4*)(out + (size_t)row*D_))[tid] = y;
    int c = tid*4;
    __half* hp = hi + (size_t)row*D_;
    __half* lp = lo + (size_t)row*D_;
    __half h0=__float2half(y.x), h1=__float2half(y.y);
    __half h2=__float2half(y.z), h3=__float2half(y.w);
    *(__half2*)(hp+c)   = __halves2half2(h0,h1);
    *(__half2*)(hp+c+2) = __halves2half2(h2,h3);
    *(__half2*)(lp+c)   = __halves2half2(
        __float2half(y.x-__half2float(h0)), __float2half(y.y-__half2float(h1)));
    *(__half2*)(lp+c+2) = __halves2half2(
        __float2half(y.z-__half2float(h2)), __float2half(y.w-__half2float(h3)));
}

// beta + decay gate from h
__global__ void k_ba(const float* __restrict__ h, const float* __restrict__ bw,
                     const float* __restrict__ aw, const float* __restrict__ A_log,
                     const float* __restrict__ dtb,
                     float* __restrict__ beta, float* __restrict__ eg){
    int row = blockIdx.x;
    int b = row >> 11, t = row & (T_-1);
    int w = threadIdx.x>>5, l = threadIdx.x&31;
    const float* hr = h + (size_t)row*D_;
    {
        const float* wr = bw + (size_t)w*D_;
        float s=0.f;
        for(int j=l;j<D_;j+=32) s += hr[j]*wr[j];
        #pragma unroll
        for(int o=16;o;o>>=1) s += __shfl_xor_sync(0xffffffffu,s,o);
        if(!l){
            int i = w>>2, hh = w&3;
            beta[(( (b*NH_+i)*H_+hh )*T_) + t] = 2.f*sigmoidf_(s);
        }
    }
    if(w < H_){
        const float* ar = aw + (size_t)w*D_;
        float s=0.f;
        for(int j=l;j<D_;j+=32) s += hr[j]*ar[j];
        #pragma unroll
        for(int o=16;o;o>>=1) s += __shfl_xor_sync(0xffffffffu,s,o);
        if(!l){
            float g = -expf(A_log[w]) * softplusf_(s + dtb[w]);
            eg[(b*H_+w)*T_ + t] = expf(g);
        }
    }
}

// causal depthwise conv (K=4) + silu (+ optional L2 norm per head) + relayout
template<bool NORM>
__global__ void k_conv(const float* __restrict__ in, const float* __restrict__ cw,
                       float* __restrict__ out, int nheads){
    int t = blockIdx.x, hd = blockIdx.y, b = blockIdx.z, c = threadIdx.x;
    int C = nheads*256;
    int ch = hd*256 + c;
    const float* wp = cw + (size_t)ch*KC_;
    float acc = 0.f;
    #pragma unroll
    for(int j=0;j<KC_;j++){
        int tt = t - (KC_-1) + j;
        if(tt>=0) acc += in[((size_t)(b*T_+tt))*C + ch]*wp[j];
    }
    float s = acc * sigmoidf_(acc);
    float y;
    if(NORM){
        float ss = blockReduce256(s*s);
        y = s * rsqrtf(ss + EPS_);
    } else y = s;
    out[(((size_t)(b*nheads+hd)*T_)+t)*256 + c] = y;
}

// ---------------- gated delta-product scan ----------------
__global__ void __launch_bounds__(256) k_scan(
    const float* __restrict__ qn, const float* __restrict__ kn,
    const float* __restrict__ vn, const float* __restrict__ beta,
    const float* __restrict__ eg, float* __restrict__ o){
    int cta = blockIdx.x;
    int ch = cta & 7;
    int hh = (cta>>3)&3;
    int b  = cta>>5;
    int vbase = ch*32;
    int tid = threadIdx.x;
    int w = tid>>5, l = tid&31;
    int col = w*4 + (l>>3);
    int kseg = l&7;
    int k0i = kseg*32;

    __shared__ float sq[2][256], sk0[2][256], sk1[2][256];
    __shared__ float sv0[2][32], sv1[2][32], ssc[2][4];

    float S[32];
    #pragma unroll
    for(int j=0;j<32;j++) S[j]=0.f;

    const float* qrow  = qn + (size_t)(b*H_+hh)*T_*256;
    const float* k0row = kn + (size_t)(b*8 + hh)*T_*256;
    const float* k1row = kn + (size_t)(b*8 + H_ + hh)*T_*256;
    const float* v0row = vn + (size_t)(b*8 + hh)*T_*256 + vbase;
    const float* v1row = vn + (size_t)(b*8 + H_ + hh)*T_*256 + vbase;
    const float* b0p = beta + ((b*NH_+0)*H_+hh)*T_;
    const float* b1p = beta + ((b*NH_+1)*H_+hh)*T_;
    const float* egp = eg + (b*H_+hh)*T_;

    sq [0][tid] = qrow[tid];
    sk0[0][tid] = k0row[tid];
    sk1[0][tid] = k1row[tid];
    if(tid<32) sv0[0][tid] = v0row[tid];
    else if(tid<64) sv1[0][tid-32] = v1row[tid-32];
    if(tid==64) ssc[0][0]=b0p[0];
    if(tid==65) ssc[0][1]=b1p[0];
    if(tid==66) ssc[0][2]=egp[0];
    __syncthreads();

    const float out_scale = rsqrtf((float)DK_);

    for(int t=0;t<T_;t++){
        int cb = t&1, nb = cb^1;
        bool hn = (t+1 < T_);
        float pq=0.f, pk0=0.f, pk1=0.f, pv=0.f, psc=0.f;
        if(hn){
            size_t off = (size_t)(t+1)*256;
            pq  = qrow [off+tid];
            pk0 = k0row[off+tid];
            pk1 = k1row[off+tid];
            if(tid<32) pv = v0row[off+tid];
            else if(tid<64) pv = v1row[off + tid-32];
            if(tid==64) psc = b0p[t+1];
            if(tid==65) psc = b1p[t+1];
            if(tid==66) psc = egp[t+1];
        }

        float egv = ssc[cb][2];
        float b0v = ssc[cb][0], b1v = ssc[cb][1];
        float v0c = sv0[cb][col], v1c = sv1[cb][col];

        #pragma unroll
        for(int j=0;j<32;j++) S[j] *= egv;

        float kr[32];
        {
            const float4* kp = (const float4*)(&sk0[cb][k0i]);
            #pragma unroll
            for(int j=0;j<8;j++){ float4 k4 = kp[j];
                kr[j*4+0]=k4.x; kr[j*4+1]=k4.y; kr[j*4+2]=k4.z; kr[j*4+3]=k4.w; }
            float pred=0.f;
            #pragma unroll
            for(int j=0;j<32;j++) pred += S[j]*kr[j];
            pred += __shfl_xor_sync(0xffffffffu,pred,1);
            pred += __shfl_xor_sync(0xffffffffu,pred,2);
            pred += __shfl_xor_sync(0xffffffffu,pred,4);
            float u = (v0c - pred)*b0v;
            #pragma unroll
            for(int j=0;j<32;j++) S[j] += kr[j]*u;
        }
        {
            const float4* kp = (const float4*)(&sk1[cb][k0i]);
            #pragma unroll
            for(int j=0;j<8;j++){ float4 k4 = kp[j];
                kr[j*4+0]=k4.x; kr[j*4+1]=k4.y; kr[j*4+2]=k4.z; kr[j*4+3]=k4.w; }
            float pred=0.f;
            #pragma unroll
            for(int j=0;j<32;j++) pred += S[j]*kr[j];
            pred += __shfl_xor_sync(0xffffffffu,pred,1);
            pred += __shfl_xor_sync(0xffffffffu,pred,2);
            pred += __shfl_xor_sync(0xffffffffu,pred,4);
            float u = (v1c - pred)*b1v;
            #pragma unroll
            for(int j=0;j<32;j++) S[j] += kr[j]*u;
        }
        {
            const float4* qp = (const float4*)(&sq[cb][k0i]);
            float po=0.f;
            #pragma unroll
            for(int j=0;j<8;j++){ float4 q4 = qp[j];
                po += S[j*4+0]*q4.x + S[j*4+1]*q4.y + S[j*4+2]*q4.z + S[j*4+3]*q4.w; }
            po += __shfl_xor_sync(0xffffffffu,po,1);
            po += __shfl_xor_sync(0xffffffffu,po,2);
            po += __shfl_xor_sync(0xffffffffu,po,4);
            if(kseg==0)
                o[(((size_t)(b*T_+t))*H_ + hh)*256 + vbase + col] = po*out_scale;
        }

        if(hn){
            sq [nb][tid]=pq; sk0[nb][tid]=pk0; sk1[nb][tid]=pk1;
            if(tid<32) sv0[nb][tid]=pv;
            else if(tid<64) sv1[nb][tid-32]=pv;
            if(tid==64) ssc[nb][0]=psc;
            if(tid==65) ssc[nb][1]=psc;
            if(tid==66) ssc[nb][2]=psc;
        }
        __syncthreads();
    }
}

// per-head RMSNorm over DV=256 -> hi/lo fp16
__global__ void k_onorm(const float* __restrict__ o, const float* __restrict__ w,
                        __half* __restrict__ hi, __half* __restrict__ lo){
    int row = blockIdx.x, tid = threadIdx.x;
    float v = o[(size_t)row*256 + tid];
    float ss = blockReduce256(v*v);
    float y = v * rsqrtf(ss*(1.f/256.f) + EPS_) * w[tid];
    __half h = __float2half(y);
    hi[(size_t)row*256 + tid] = h;
    lo[(size_t)row*256 + tid] = __float2half(y - __half2float(h));
}

__global__ void k_swiglu_cvt(const float* __restrict__ gl, const float* __restrict__ ul,
                             __half* __restrict__ mh, __half* __restrict__ ml,
                             size_t n4){
    size_t i4 = (size_t)blockIdx.x*256 + threadIdx.x;
    if(i4 < n4){
        size_t c = i4*4;
        float4 g4 = *(const float4*)(gl + c);
        float4 u4 = *(const float4*)(ul + c);
        float m0 = g4.x*sigmoidf_(g4.x)*u4.x;
        float m1 = g4.y*sigmoidf_(g4.y)*u4.y;
        float m2 = g4.z*sigmoidf_(g4.z)*u4.z;
        float m3 = g4.w*sigmoidf_(g4.w)*u4.w;
        __half h0=__float2half(m0), h1=__float2half(m1);
        __half h2=__float2half(m2), h3=__float2half(m3);
        *(__half2*)(mh+c)   = __halves2half2(h0,h1);
        *(__half2*)(mh+c+2) = __halves2half2(h2,h3);
        *(__half2*)(ml+c)   = __halves2half2(
            __float2half(m0-__half2float(h0)), __float2half(m1-__half2float(h1)));
        *(__half2*)(ml+c+2) = __halves2half2(
            __float2half(m2-__half2float(h2)), __float2half(m3-__half2float(h3)));
    }
}

__global__ void k_last(const float* __restrict__ out, float* __restrict__ dst){
    int idx = blockIdx.x*256 + threadIdx.x; // B*D = 8192
    int b = idx >> 10, i = idx & (D_-1);
    dst[idx] = out[((size_t)(b*T_ + (T_-1)))*D_ + i];
}

// ---------------- launcher ----------------
extern "C" void kernel_launch(void* const* d_in, const int* in_sizes, int n_in,
                              void* d_out, int out_size){
    const float* x    = (const float*)d_in[0];
    const float* prev = (const float*)d_in[1];
    const float* spw  = (const float*)d_in[2];
    const float* sgw  = (const float*)d_in[3];
    const float* sgb  = (const float*)d_in[4];
    const float* anw  = (const float*)d_in[5];
    const float* qw   = (const float*)d_in[6];
    const float* kw   = (const float*)d_in[7];
    const float* vw   = (const float*)d_in[8];
    const float* bw   = (const float*)d_in[9];
    const float* aw   = (const float*)d_in[10];
    const float* Alog = (const float*)d_in[11];
    const float* dtb  = (const float*)d_in[12];
    const float* qcw  = (const float*)d_in[13];
    const float* kcw  = (const float*)d_in[14];
    const float* vcw  = (const float*)d_in[15];
    const float* onw  = (const float*)d_in[16];
    const float* ow   = (const float*)d_in[17];
    const float* mnw  = (const float*)d_in[18];
    const float* gw   = (const float*)d_in[19];
    const float* uw   = (const float*)d_in[20];
    const float* dw   = (const float*)d_in[21];
    float* out = (float*)d_out;

    float *es,*ge,*gx,*xf,*h,*qlin,*klin,*vlin,*qn,*kn,*vn,*beta,*eg,*ob,*x2,*gl,*ul;
    cudaGetSymbolAddress((void**)&es, g_es);
    cudaGetSymbolAddress((void**)&ge, g_ge);
    cudaGetSymbolAddress((void**)&gx, g_gx);
    cudaGetSymbolAddress((void**)&xf, g_xf);
    cudaGetSymbolAddress((void**)&h,  g_h);
    cudaGetSymbolAddress((void**)&qlin, g_qlin);
    cudaGetSymbolAddress((void**)&klin, g_klin);
    cudaGetSymbolAddress((void**)&vlin, g_vlin);
    cudaGetSymbolAddress((void**)&qn, g_qn);
    cudaGetSymbolAddress((void**)&kn, g_kn);
    cudaGetSymbolAddress((void**)&vn, g_vn);
    cudaGetSymbolAddress((void**)&beta, g_beta);
    cudaGetSymbolAddress((void**)&eg, g_eg);
    cudaGetSymbolAddress((void**)&ob, g_o);
    cudaGetSymbolAddress((void**)&x2, g_x2);
    cudaGetSymbolAddress((void**)&gl, g_gl);
    cudaGetSymbolAddress((void**)&ul, g_ul);

    __half *xh,*xl,*hh,*hl,*onh,*onl,*h2h,*h2l,*mh,*ml;
    __half *wsgh,*wqh,*wkh,*wvh,*woh,*wgh,*wuh,*wdh;
    cudaGetSymbolAddress((void**)&xh, g_xh);   cudaGetSymbolAddress((void**)&xl, g_xl);
    cudaGetSymbolAddress((void**)&hh, g_hh);   cudaGetSymbolAddress((void**)&hl, g_hl);
    cudaGetSymbolAddress((void**)&onh, g_onh); cudaGetSymbolAddress((void**)&onl, g_onl);
    cudaGetSymbolAddress((void**)&h2h, g_h2h); cudaGetSymbolAddress((void**)&h2l, g_h2l);
    cudaGetSymbolAddress((void**)&mh, g_mh);   cudaGetSymbolAddress((void**)&ml, g_ml);
    cudaGetSymbolAddress((void**)&wsgh, g_wsgh);
    cudaGetSymbolAddress((void**)&wqh, g_wqh);
    cudaGetSymbolAddress((void**)&wkh, g_wkh);
    cudaGetSymbolAddress((void**)&wvh, g_wvh);
    cudaGetSymbolAddress((void**)&woh, g_woh);
    cudaGetSymbolAddress((void**)&wgh, g_wgh);
    cudaGetSymbolAddress((void**)&wuh, g_wuh);
    cudaGetSymbolAddress((void**)&wdh, g_wdh);

    cudaFuncSetAttribute(hm_gemm<false>, cudaFuncAttributeMaxDynamicSharedMemorySize, GSM_BYTES);
    cudaFuncSetAttribute(hm_gemm<true>,  cudaFuncAttributeMaxDynamicSharedMemorySize, GSM_BYTES);

    // launches 0-2; captured ncu slot appears to be my index 3 -> put hm_gemm there
    k_cvtw<<<1024, 256>>>(sgw, 2*D_, D_, wsgh);        // 0
    k_cvt2<<<MT_, 256>>>(x, D_, D_, xh, xl);           // 1
    k_es<<<dim3(D_/8, B_), 256>>>(prev, spw, es);      // 2

    // ---- state fusion gate GEMM (launch 3, profiled) ----
    hm_gemm<false><<<dim3(D_/BN, MT_/BM), 256, GSM_BYTES>>>(xh, xl, wsgh, nullptr, gx, D_, D_);

    k_ge<<<dim3(D_/8, B_), 256>>>(es, sgw, sgb, ge);
    k_fuse<<<MT_*D_/256, 256>>>(x, gx, ge, es, xf);

    // ---- remaining weight conversions ----
    k_cvtw<<<1024, 256>>>(qw, D_, D_, wqh);
    k_cvtw<<<2048, 256>>>(kw, D_, D_, wkh);
    k_cvtw<<<2048, 256>>>(vw, D_, D_, wvh);
    k_cvtw<<<1024, 256>>>(ow, D_, D_, woh);
    k_cvtw<<<I_, 256>>>(gw, D_, D_, wgh);
    k_cvtw<<<I_, 256>>>(uw, D_, D_, wuh);
    k_cvtw<<<1024, 256>>>(dw, I_, I_, wdh);

    // ---- attention sub-block ----
    k_rms2<true><<<MT_, 256>>>(xf, anw, h, hh, hl);
    hm_gemm<false><<<dim3(D_/BN, MT_/BM), 256, GSM_BYTES>>>(hh, hl, wqh, nullptr, qlin, D_, D_);
    hm_gemm<false><<<dim3(2048/BN, MT_/BM), 256, GSM_BYTES>>>(hh, hl, wkh, nullptr, klin, D_, 2048);
    hm_gemm<false><<<dim3(2048/BN, MT_/BM), 256, GSM_BYTES>>>(hh, hl, wvh, nullptr, vlin, D_, 2048);
    k_ba<<<MT_, 256>>>(h, bw, aw, Alog, dtb, beta, eg);
    k_conv<true ><<<dim3(T_, H_,      B_), 256>>>(qlin, qcw, qn, H_);
    k_conv<true ><<<dim3(T_, NH_*H_, B_), 256>>>(klin, kcw, kn, NH_*H_);
    k_conv<false><<<dim3(T_, NH_*H_, B_), 256>>>(vlin, vcw, vn, NH_*H_);

    k_scan<<<B_*H_*8, 256>>>(qn, kn, vn, beta, eg, ob);

    k_onorm<<<MT_*H_, 256>>>(ob, onw, onh, onl);
    hm_gemm<true><<<dim3(D_/BN, MT_/BM), 256, GSM_BYTES>>>(onh, onl, woh, xf, x2, D_, D_);

    // ---- MLP ----
    k_rms2<false><<<MT_, 256>>>(x2, mnw, nullptr, h2h, h2l);
    hm_gemm<false><<<dim3(I_/BN, MT_/BM), 256, GSM_BYTES>>>(h2h, h2l, wgh, nullptr, gl, D_, I_);
    hm_gemm<false><<<dim3(I_/BN, MT_/BM), 256, GSM_BYTES>>>(h2h, h2l, wuh, nullptr, ul, D_, I_);
    {
        size_t n4 = (size_t)MT_*I_/4;
        k_swiglu_cvt<<<(unsigned)((n4+255)/256), 256>>>(gl, ul, mh, ml, n4);
    }
    hm_gemm<true><<<dim3(D_/BN, MT_/BM), 256, GSM_BYTES>>>(mh, ml, wdh, x2, out, I_, D_);

    // ---- second output: final hidden state ----
    k_last<<<B_*D_/256, 256>>>(out, out + (size_t)MT_*D_);
}

// round 14
// speedup vs baseline: 3.4633x; 2.2585x over previous
#include <cuda_runtime.h>
#include <cuda_fp16.h>
#include <math.h>
#include <stdint.h>

// Problem constants
#define B_ 8
#define T_ 2048
#define D_ 1024
#define H_ 4
#define DK_ 256
#define DV_ 256
#define NH_ 2
#define KC_ 4
#define I_ 2816
#define EPS_ 1e-6f

#define MT_ (B_*T_)          // 16384 rows

// ---------------- scratch (device globals; no allocation allowed) ----------------
__device__ float g_es[B_*D_];
__device__ float g_ge[B_*D_];
__device__ float g_gx[MT_*D_];
__device__ float g_xf[MT_*D_];
__device__ float g_h [MT_*D_];
__device__ float g_qlin[MT_*D_];
__device__ float g_klin[MT_*2048];
__device__ float g_vlin[MT_*2048];
__device__ float g_qn[MT_*D_];          // [B,H,T,DK]
__device__ float g_kn[MT_*2048];        // [B,NH*H,T,DK]
__device__ float g_vn[MT_*2048];        // [B,NH*H,T,DV]
__device__ float g_beta[B_*NH_*H_*T_];
__device__ float g_eg[B_*H_*T_];
__device__ float g_o [MT_*D_];          // [B,T,H,DV]
__device__ float g_x2[MT_*D_];
__device__ float g_gl[MT_*I_];
__device__ float g_ul[MT_*I_];

// fp16 hi/lo split scratch (activations)
__device__ __half g_xh[MT_*D_],  g_xl[MT_*D_];
__device__ __half g_hh[MT_*D_],  g_hl[MT_*D_];
__device__ __half g_onh[MT_*D_], g_onl[MT_*D_];
__device__ __half g_h2h[MT_*D_], g_h2l[MT_*D_];
__device__ __half g_mh[MT_*I_],  g_ml[MT_*I_];
// fp16 weights (hi only used by GEMM)
__device__ __half g_wsgh[D_*D_];
__device__ __half g_wqh[D_*D_];
__device__ __half g_wkh[2048*D_];
__device__ __half g_wvh[2048*D_];
__device__ __half g_woh[D_*D_];
__device__ __half g_wgh[I_*D_];
__device__ __half g_wuh[I_*D_];
__device__ __half g_wdh[D_*I_];

// ---------------- helpers ----------------
__device__ __forceinline__ float sigmoidf_(float x){ return 1.f/(1.f+expf(-x)); }
__device__ __forceinline__ float softplusf_(float x){ return x>20.f? x : log1pf(expf(x)); }

__device__ __forceinline__ float blockReduce256(float v){
    __shared__ float sh[8];
    #pragma unroll
    for(int o=16;o;o>>=1) v += __shfl_xor_sync(0xffffffffu, v, o);
    if((threadIdx.x&31)==0) sh[threadIdx.x>>5] = v;
    __syncthreads();
    float s = 0.f;
    #pragma unroll
    for(int i=0;i<8;i++) s += sh[i];
    return s;
}

__device__ __forceinline__ uint32_t smem_u32(const void* p){
    uint32_t a;
    asm("{ .reg .u64 t; cvta.to.shared.u64 t, %1; cvt.u32.u64 %0, t; }" : "=r"(a) : "l"(p));
    return a;
}
__device__ __forceinline__ void cp16(uint32_t s, const void* g){
    asm volatile("cp.async.cg.shared.global [%0], [%1], 16;" :: "r"(s), "l"(g));
}
__device__ __forceinline__ void cp_commit(){
    asm volatile("cp.async.commit_group;" ::: "memory");
}
template<int N>
__device__ __forceinline__ void cp_wait(){
    asm volatile("cp.async.wait_group %0;" :: "n"(N) : "memory");
}
__device__ __forceinline__ void ldm_x4(uint32_t* r, uint32_t addr){
    asm volatile("ldmatrix.sync.aligned.m8n8.x4.shared.b16 {%0,%1,%2,%3}, [%4];"
        : "=r"(r[0]), "=r"(r[1]), "=r"(r[2]), "=r"(r[3]) : "r"(addr));
}
__device__ __forceinline__ void mma16816(float* d, const uint32_t* a, const uint32_t* b){
    asm volatile("mma.sync.aligned.m16n8k16.row.col.f32.f16.f16.f32 "
        "{%0,%1,%2,%3}, {%4,%5,%6,%7}, {%8,%9}, {%0,%1,%2,%3};"
        : "+f"(d[0]), "+f"(d[1]), "+f"(d[2]), "+f"(d[3])
        : "r"(a[0]), "r"(a[1]), "r"(a[2]), "r"(a[3]), "r"(b[0]), "r"(b[1]));
}

// ---------------- HMMA fp16 2-term GEMM ----------------
// C[M,N] = A[M,K]*B[N,K]^T ~fp32 via fp16 split: ah*bh + al*bh
// (drops a*bl, rel err ~2^-12). CTA 128x128, BK=32, 8 warps, 3-stage cp.async.
#define BM 128
#define BN 128
#define ASTR 40   // fp16 row stride in smem (80B) -> conflict-free ldmatrix
#define STG_BYTES (BM*ASTR*2)        // 10240 per matrix per stage
#define STAGE_BYTES (2*STG_BYTES)    // A + B
#define GSM_BYTES (3*STAGE_BYTES)    // 61440

template<bool RES>
__global__ void __launch_bounds__(256,2)
hm_gemm(const __half* __restrict__ Ah, const __half* __restrict__ Al,
        const __half* __restrict__ Bh,
        const float* __restrict__ Res, float* __restrict__ C, int K, int ldc)
{
    extern __shared__ __align__(16) char smem_raw[];

    int tid = threadIdx.x, wid = tid>>5, lane = tid&31;
    int rowBase = blockIdx.y*BM, colBase = blockIdx.x*BN;
    int wr = wid & 3, wc = wid >> 2;
    int mBase = wr*32, nBase = wc*64;

    int nk = K >> 5;          // K/32 chunks per segment
    int nIter = 2*nk;

    float acc[2][8][4];
    #pragma unroll
    for(int mi=0;mi<2;mi++)
        #pragma unroll
        for(int ni=0;ni<8;ni++)
            #pragma unroll
            for(int q=0;q<4;q++) acc[mi][ni][q]=0.f;

    // loader indices: 512 16B-chunks per matrix, 2 per thread
    int lr = tid >> 2;          // row (0..63; +64 with j)
    int lc = tid & 3;           // 16B-chunk within 32-col row

    uint32_t aS[3][2], bS[3][2];
    #pragma unroll
    for(int s=0;s<3;s++){
        #pragma unroll
        for(int j=0;j<2;j++){
            int r = lr + j*64;
            uint32_t off = (uint32_t)((r*ASTR + lc*8)*2);
            aS[s][j] = smem_u32(smem_raw + s*STAGE_BYTES + off);
            bS[s][j] = smem_u32(smem_raw + s*STAGE_BYTES + STG_BYTES + off);
        }
    }

    auto stage = [&](int it){
        if(it < nIter){
            int buf = it % 3;
            int seg = it / nk, cc = it - seg*nk;
            const __half* As = seg ? Al : Ah;
            int k0 = cc<<5;
            #pragma unroll
            for(int j=0;j<2;j++){
                int r = lr + j*64;
                cp16(aS[buf][j], As + (size_t)(rowBase+r)*K + k0 + lc*8);
                cp16(bS[buf][j], Bh + (size_t)(colBase+r)*K + k0 + lc*8);
            }
        }
        cp_commit();   // uniform group count even when empty
    };

    // prologue: stages 0,1
    stage(0);
    stage(1);

    // precompute ldmatrix smem offsets per stage
    uint32_t aL[3], bL[3];
    {
        int arow = mBase + (lane&15);
        int acol = (lane>>4)<<3;
        int brow = nBase + (lane&7) + (((lane>>4)&1)<<3);
        int bcol = ((lane>>3)&1)<<3;
        #pragma unroll
        for(int s=0;s<3;s++){
            aL[s] = smem_u32(smem_raw + s*STAGE_BYTES + (uint32_t)((arow*ASTR + acol)*2));
            bL[s] = smem_u32(smem_raw + s*STAGE_BYTES + STG_BYTES + (uint32_t)((brow*ASTR + bcol)*2));
        }
    }

    for(int it=0; it<nIter; it++){
        int buf = it % 3;
        cp_wait<1>();          // stage `it` resident
        __syncthreads();

        #pragma unroll
        for(int ks=0; ks<2; ks++){
            uint32_t af[2][4], bfr[8][2];
            #pragma unroll
            for(int mi=0;mi<2;mi++)
                ldm_x4(af[mi], aL[buf] + (uint32_t)((mi*16*ASTR + ks*16)*2));
            #pragma unroll
            for(int n4=0;n4<4;n4++){
                uint32_t r4[4];
                ldm_x4(r4, bL[buf] + (uint32_t)((n4*16*ASTR + ks*16)*2));
                bfr[n4*2+0][0]=r4[0]; bfr[n4*2+0][1]=r4[1];
                bfr[n4*2+1][0]=r4[2]; bfr[n4*2+1][1]=r4[3];
            }
            #pragma unroll
            for(int mi=0;mi<2;mi++)
                #pragma unroll
                for(int ni=0;ni<8;ni++)
                    mma16816(acc[mi][ni], af[mi], bfr[ni]);
        }

        stage(it+2);
    }

    // epilogue
    int qr = lane>>2, qc = lane&3;
    #pragma unroll
    for(int mi=0;mi<2;mi++){
        #pragma unroll
        for(int ni=0;ni<8;ni++){
            int row0 = rowBase + mBase + mi*16 + qr;
            int col  = colBase + nBase + ni*8 + qc*2;
            float2 v0 = make_float2(acc[mi][ni][0], acc[mi][ni][1]);
            float2 v1 = make_float2(acc[mi][ni][2], acc[mi][ni][3]);
            if(RES){
                float2 r0 = *(const float2*)(Res + (size_t)row0*ldc + col);
                float2 r1 = *(const float2*)(Res + (size_t)(row0+8)*ldc + col);
                v0.x+=r0.x; v0.y+=r0.y; v1.x+=r1.x; v1.y+=r1.y;
            }
            *(float2*)(C + (size_t)row0*ldc + col) = v0;
            *(float2*)(C + (size_t)(row0+8)*ldc + col) = v1;
        }
    }
}

// ---------------- hi/lo conversion ----------------
__global__ void k_cvt2(const float* __restrict__ in, int ld, int cols,
                       __half* __restrict__ hi, __half* __restrict__ lo){
    int r = blockIdx.x;
    const float* ip = in + (size_t)r*ld;
    __half* hp = hi + (size_t)r*cols;
    __half* lp = lo + (size_t)r*cols;
    for(int c = threadIdx.x*4; c < cols; c += 1024){
        float4 v = *(const float4*)(ip + c);
        __half h0=__float2half(v.x), h1=__float2half(v.y);
        __half h2=__float2half(v.z), h3=__float2half(v.w);
        *(__half2*)(hp+c)   = __halves2half2(h0,h1);
        *(__half2*)(hp+c+2) = __halves2half2(h2,h3);
        *(__half2*)(lp+c)   = __halves2half2(
            __float2half(v.x-__half2float(h0)), __float2half(v.y-__half2float(h1)));
        *(__half2*)(lp+c+2) = __halves2half2(
            __float2half(v.z-__half2float(h2)), __float2half(v.w-__half2float(h3)));
    }
}

// weights: hi only
__global__ void k_cvtw(const float* __restrict__ in, int ld, int cols,
                       __half* __restrict__ hi){
    int r = blockIdx.x;
    const float* ip = in + (size_t)r*ld;
    __half* hp = hi + (size_t)r*cols;
    for(int c = threadIdx.x*4; c < cols; c += 1024){
        float4 v = *(const float4*)(ip + c);
        *(__half2*)(hp+c)   = __halves2half2(__float2half(v.x), __float2half(v.y));
        *(__half2*)(hp+c+2) = __halves2half2(__float2half(v.z), __float2half(v.w));
    }
}

// ---------------- small warp-dot kernels ----------------
__global__ void k_es(const float* __restrict__ prev, const float* __restrict__ W,
                     float* __restrict__ es){
    int b = blockIdx.y;
    int w = threadIdx.x>>5, l = threadIdx.x&31;
    int i = blockIdx.x*8 + w;
    const float* pr = prev + b*D_;
    const float* wr = W + (size_t)i*D_;
    float s=0.f;
    for(int j=l;j<D_;j+=32) s += pr[j]*wr[j];
    #pragma unroll
    for(int o=16;o;o>>=1) s += __shfl_xor_sync(0xffffffffu,s,o);
    if(!l) es[b*D_+i]=s;
}

__global__ void k_ge(const float* __restrict__ es, const float* __restrict__ Wg,
                     const float* __restrict__ bias, float* __restrict__ ge){
    int b = blockIdx.y;
    int w = threadIdx.x>>5, l = threadIdx.x&31;
    int i = blockIdx.x*8 + w;
    const float* er = es + b*D_;
    const float* wr = Wg + (size_t)i*(2*D_) + D_;
    float s=0.f;
    for(int j=l;j<D_;j+=32) s += er[j]*wr[j];
    #pragma unroll
    for(int o=16;o;o>>=1) s += __shfl_xor_sync(0xffffffffu,s,o);
    if(!l) ge[b*D_+i] = s + bias[i];
}

// ---------------- elementwise fusion ----------------
__global__ void k_fuse(const float* __restrict__ x, const float* __restrict__ gx,
                       const float* __restrict__ ge, const float* __restrict__ es,
                       float* __restrict__ xf){
    size_t idx = (size_t)blockIdx.x*256 + threadIdx.x;
    int i = (int)(idx & (D_-1));
    int m = (int)(idx >> 10);
    int b = m >> 11;
    float g = sigmoidf_(gx[idx] + ge[b*D_+i]);
    float e = es[b*D_+i];
    xf[idx] = g*x[idx] + (1.f-g)*e;
}

// RMSNorm over D=1024: optional fp32 out + hi/lo fp16 out
template<bool F32OUT>
__global__ void k_rms2(const float* __restrict__ in, const float* __restrict__ w,
                       float* __restrict__ out,
                       __half* __restrict__ hi, __half* __restrict__ lo){
    int row = blockIdx.x, tid = threadIdx.x;
    const float4* ir = (const float4*)(in + (size_t)row*D_);
    float4 v = ir[tid];
    float ss = blockReduce256(v.x*v.x+v.y*v.y+v.z*v.z+v.w*v.w);
    float sc = rsqrtf(ss*(1.f/D_) + EPS_);
    float4 ww = ((const float4*)w)[tid];
    float4 y = make_float4(v.x*sc*ww.x, v.y*sc*ww.y, v.z*sc*ww.z, v.w*sc*ww.w);
    if(F32OUT) ((float4*)(out + (size_t)row*D_))[tid] = y;
    int c = tid*4;
    __half* hp = hi + (size_t)row*D_;
    __half* lp = lo + (size_t)row*D_;
    __half h0=__float2half(y.x), h1=__float2half(y.y);
    __half h2=__float2half(y.z), h3=__float2half(y.w);
    *(__half2*)(hp+c)   = __halves2half2(h0,h1);
    *(__half2*)(hp+c+2) = __halves2half2(h2,h3);
    *(__half2*)(lp+c)   = __halves2half2(
        __float2half(y.x-__half2float(h0)), __float2half(y.y-__half2float(h1)));
    *(__half2*)(lp+c+2) = __halves2half2(
        __float2half(y.z-__half2float(h2)), __float2half(y.w-__half2float(h3)));
}

// beta + decay gate from h
__global__ void k_ba(const float* __restrict__ h, const float* __restrict__ bw,
                     const float* __restrict__ aw, const float* __restrict__ A_log,
                     const float* __restrict__ dtb,
                     float* __restrict__ beta, float* __restrict__ eg){
    int row = blockIdx.x;
    int b = row >> 11, t = row & (T_-1);
    int w = threadIdx.x>>5, l = threadIdx.x&31;
    const float* hr = h + (size_t)row*D_;
    {
        const float* wr = bw + (size_t)w*D_;
        float s=0.f;
        for(int j=l;j<D_;j+=32) s += hr[j]*wr[j];
        #pragma unroll
        for(int o=16;o;o>>=1) s += __shfl_xor_sync(0xffffffffu,s,o);
        if(!l){
            int i = w>>2, hh = w&3;
            beta[(( (b*NH_+i)*H_+hh )*T_) + t] = 2.f*sigmoidf_(s);
        }
    }
    if(w < H_){
        const float* ar = aw + (size_t)w*D_;
        float s=0.f;
        for(int j=l;j<D_;j+=32) s += hr[j]*ar[j];
        #pragma unroll
        for(int o=16;o;o>>=1) s += __shfl_xor_sync(0xffffffffu,s,o);
        if(!l){
            float g = -expf(A_log[w]) * softplusf_(s + dtb[w]);
            eg[(b*H_+w)*T_ + t] = expf(g);
        }
    }
}

// causal depthwise conv (K=4) + silu (+ optional L2 norm per head) + relayout
template<bool NORM>
__global__ void k_conv(const float* __restrict__ in, const float* __restrict__ cw,
                       float* __restrict__ out, int nheads){
    int t = blockIdx.x, hd = blockIdx.y, b = blockIdx.z, c = threadIdx.x;
    int C = nheads*256;
    int ch = hd*256 + c;
    const float* wp = cw + (size_t)ch*KC_;
    float acc = 0.f;
    #pragma unroll
    for(int j=0;j<KC_;j++){
        int tt = t - (KC_-1) + j;
        if(tt>=0) acc += in[((size_t)(b*T_+tt))*C + ch]*wp[j];
    }
    float s = acc * sigmoidf_(acc);
    float y;
    if(NORM){
        float ss = blockReduce256(s*s);
        y = s * rsqrtf(ss + EPS_);
    } else y = s;
    out[(((size_t)(b*nheads+hd)*T_)+t)*256 + c] = y;
}

// ---------------- gated delta-product scan ----------------
// Bank-conflict-free smem layout: element e stored at (e>>5)*36 + (e&31).
// Segment s (32 floats) starts at s*36 floats = s*144 B (16B-aligned, start
// bank 4s mod 32 distinct across the 8 segments -> conflict-free LDS.128).
#define SSEG 36
__global__ void __launch_bounds__(256) k_scan(
    const float* __restrict__ qn, const float* __restrict__ kn,
    const float* __restrict__ vn, const float* __restrict__ beta,
    const float* __restrict__ eg, float* __restrict__ o){
    int cta = blockIdx.x;
    int ch = cta & 7;
    int hh = (cta>>3)&3;
    int b  = cta>>5;
    int vbase = ch*32;
    int tid = threadIdx.x;
    int w = tid>>5, l = tid&31;
    int col = w*4 + (l>>3);
    int kseg = l&7;

    __shared__ float sq[2][8*SSEG], sk0[2][8*SSEG], sk1[2][8*SSEG];
    __shared__ float sv0[2][32], sv1[2][32], ssc[2][4];

    int spos = (tid>>5)*SSEG + (tid&31);   // store slot for element index tid
    int kbase = kseg*SSEG;                 // read base for this lane's segment

    float S[32];
    #pragma unroll
    for(int j=0;j<32;j++) S[j]=0.f;

    const float* qrow  = qn + (size_t)(b*H_+hh)*T_*256;
    const float* k0row = kn + (size_t)(b*8 + hh)*T_*256;
    const float* k1row = kn + (size_t)(b*8 + H_ + hh)*T_*256;
    const float* v0row = vn + (size_t)(b*8 + hh)*T_*256 + vbase;
    const float* v1row = vn + (size_t)(b*8 + H_ + hh)*T_*256 + vbase;
    const float* b0p = beta + ((b*NH_+0)*H_+hh)*T_;
    const float* b1p = beta + ((b*NH_+1)*H_+hh)*T_;
    const float* egp = eg + (b*H_+hh)*T_;

    sq [0][spos] = qrow[tid];
    sk0[0][spos] = k0row[tid];
    sk1[0][spos] = k1row[tid];
    if(tid<32) sv0[0][tid] = v0row[tid];
    else if(tid<64) sv1[0][tid-32] = v1row[tid-32];
    if(tid==64) ssc[0][0]=b0p[0];
    if(tid==65) ssc[0][1]=b1p[0];
    if(tid==66) ssc[0][2]=egp[0];
    __syncthreads();

    const float out_scale = rsqrtf((float)DK_);

    for(int t=0;t<T_;t++){
        int cb = t&1, nb = cb^1;
        bool hn = (t+1 < T_);
        float pq=0.f, pk0=0.f, pk1=0.f, pv=0.f, psc=0.f;
        if(hn){
            size_t off = (size_t)(t+1)*256;
            pq  = qrow [off+tid];
            pk0 = k0row[off+tid];
            pk1 = k1row[off+tid];
            if(tid<32) pv = v0row[off+tid];
            else if(tid<64) pv = v1row[off + tid-32];
            if(tid==64) psc = b0p[t+1];
            if(tid==65) psc = b1p[t+1];
            if(tid==66) psc = egp[t+1];
        }

        float egv = ssc[cb][2];
        float b0v = ssc[cb][0], b1v = ssc[cb][1];
        float v0c = sv0[cb][col], v1c = sv1[cb][col];

        #pragma unroll
        for(int j=0;j<32;j++) S[j] *= egv;

        float kr[32];
        {
            const float4* kp = (const float4*)(&sk0[cb][kbase]);
            #pragma unroll
            for(int j=0;j<8;j++){ float4 k4 = kp[j];
                kr[j*4+0]=k4.x; kr[j*4+1]=k4.y; kr[j*4+2]=k4.z; kr[j*4+3]=k4.w; }
            float p0=0.f,p1=0.f,p2=0.f,p3=0.f;
            #pragma unroll
            for(int j=0;j<8;j++){
                p0 += S[j*4+0]*kr[j*4+0];
                p1 += S[j*4+1]*kr[j*4+1];
                p2 += S[j*4+2]*kr[j*4+2];
                p3 += S[j*4+3]*kr[j*4+3];
            }
            float pred = (p0+p1)+(p2+p3);
            pred += __shfl_xor_sync(0xffffffffu,pred,1);
            pred += __shfl_xor_sync(0xffffffffu,pred,2);
            pred += __shfl_xor_sync(0xffffffffu,pred,4);
            float u = (v0c - pred)*b0v;
            #pragma unroll
            for(int j=0;j<32;j++) S[j] += kr[j]*u;
        }
        {
            const float4* kp = (const float4*)(&sk1[cb][kbase]);
            #pragma unroll
            for(int j=0;j<8;j++){ float4 k4 = kp[j];
                kr[j*4+0]=k4.x; kr[j*4+1]=k4.y; kr[j*4+2]=k4.z; kr[j*4+3]=k4.w; }
            float p0=0.f,p1=0.f,p2=0.f,p3=0.f;
            #pragma unroll
            for(int j=0;j<8;j++){
                p0 += S[j*4+0]*kr[j*4+0];
                p1 += S[j*4+1]*kr[j*4+1];
                p2 += S[j*4+2]*kr[j*4+2];
                p3 += S[j*4+3]*kr[j*4+3];
            }
            float pred = (p0+p1)+(p2+p3);
            pred += __shfl_xor_sync(0xffffffffu,pred,1);
            pred += __shfl_xor_sync(0xffffffffu,pred,2);
            pred += __shfl_xor_sync(0xffffffffu,pred,4);
            float u = (v1c - pred)*b1v;
            #pragma unroll
            for(int j=0;j<32;j++) S[j] += kr[j]*u;
        }
        {
            const float4* qp = (const float4*)(&sq[cb][kbase]);
            float p0=0.f,p1=0.f;
            #pragma unroll
            for(int j=0;j<8;j++){ float4 q4 = qp[j];
                p0 += S[j*4+0]*q4.x + S[j*4+1]*q4.y;
                p1 += S[j*4+2]*q4.z + S[j*4+3]*q4.w; }
            float po = p0+p1;
            po += __shfl_xor_sync(0xffffffffu,po,1);
            po += __shfl_xor_sync(0xffffffffu,po,2);
            po += __shfl_xor_sync(0xffffffffu,po,4);
            if(kseg==0)
                o[(((size_t)(b*T_+t))*H_ + hh)*256 + vbase + col] = po*out_scale;
        }

        if(hn){
            sq [nb][spos]=pq; sk0[nb][spos]=pk0; sk1[nb][spos]=pk1;
            if(tid<32) sv0[nb][tid]=pv;
            else if(tid<64) sv1[nb][tid-32]=pv;
            if(tid==64) ssc[nb][0]=psc;
            if(tid==65) ssc[nb][1]=psc;
            if(tid==66) ssc[nb][2]=psc;
        }
        __syncthreads();
    }
}

// per-head RMSNorm over DV=256 -> hi/lo fp16
__global__ void k_onorm(const float* __restrict__ o, const float* __restrict__ w,
                        __half* __restrict__ hi, __half* __restrict__ lo){
    int row = blockIdx.x, tid = threadIdx.x;
    float v = o[(size_t)row*256 + tid];
    float ss = blockReduce256(v*v);
    float y = v * rsqrtf(ss*(1.f/256.f) + EPS_) * w[tid];
    __half h = __float2half(y);
    hi[(size_t)row*256 + tid] = h;
    lo[(size_t)row*256 + tid] = __float2half(y - __half2float(h));
}

__global__ void k_swiglu_cvt(const float* __restrict__ gl, const float* __restrict__ ul,
                             __half* __restrict__ mh, __half* __restrict__ ml,
                             size_t n4){
    size_t i4 = (size_t)blockIdx.x*256 + threadIdx.x;
    if(i4 < n4){
        size_t c = i4*4;
        float4 g4 = *(const float4*)(gl + c);
        float4 u4 = *(const float4*)(ul + c);
        float m0 = g4.x*sigmoidf_(g4.x)*u4.x;
        float m1 = g4.y*sigmoidf_(g4.y)*u4.y;
        float m2 = g4.z*sigmoidf_(g4.z)*u4.z;
        float m3 = g4.w*sigmoidf_(g4.w)*u4.w;
        __half h0=__float2half(m0), h1=__float2half(m1);
        __half h2=__float2half(m2), h3=__float2half(m3);
        *(__half2*)(mh+c)   = __halves2half2(h0,h1);
        *(__half2*)(mh+c+2) = __halves2half2(h2,h3);
        *(__half2*)(ml+c)   = __halves2half2(
            __float2half(m0-__half2float(h0)), __float2half(m1-__half2float(h1)));
        *(__half2*)(ml+c+2) = __halves2half2(
            __float2half(m2-__half2float(h2)), __float2half(m3-__half2float(h3)));
    }
}

__global__ void k_last(const float* __restrict__ out, float* __restrict__ dst){
    int idx = blockIdx.x*256 + threadIdx.x; // B*D = 8192
    int b = idx >> 10, i = idx & (D_-1);
    dst[idx] = out[((size_t)(b*T_ + (T_-1)))*D_ + i];
}

// ---------------- launcher ----------------
extern "C" void kernel_launch(void* const* d_in, const int* in_sizes, int n_in,
                              void* d_out, int out_size){
    const float* x    = (const float*)d_in[0];
    const float* prev = (const float*)d_in[1];
    const float* spw  = (const float*)d_in[2];
    const float* sgw  = (const float*)d_in[3];
    const float* sgb  = (const float*)d_in[4];
    const float* anw  = (const float*)d_in[5];
    const float* qw   = (const float*)d_in[6];
    const float* kw   = (const float*)d_in[7];
    const float* vw   = (const float*)d_in[8];
    const float* bw   = (const float*)d_in[9];
    const float* aw   = (const float*)d_in[10];
    const float* Alog = (const float*)d_in[11];
    const float* dtb  = (const float*)d_in[12];
    const float* qcw  = (const float*)d_in[13];
    const float* kcw  = (const float*)d_in[14];
    const float* vcw  = (const float*)d_in[15];
    const float* onw  = (const float*)d_in[16];
    const float* ow   = (const float*)d_in[17];
    const float* mnw  = (const float*)d_in[18];
    const float* gw   = (const float*)d_in[19];
    const float* uw   = (const float*)d_in[20];
    const float* dw   = (const float*)d_in[21];
    float* out = (float*)d_out;

    float *es,*ge,*gx,*xf,*h,*qlin,*klin,*vlin,*qn,*kn,*vn,*beta,*eg,*ob,*x2,*gl,*ul;
    cudaGetSymbolAddress((void**)&es, g_es);
    cudaGetSymbolAddress((void**)&ge, g_ge);
    cudaGetSymbolAddress((void**)&gx, g_gx);
    cudaGetSymbolAddress((void**)&xf, g_xf);
    cudaGetSymbolAddress((void**)&h,  g_h);
    cudaGetSymbolAddress((void**)&qlin, g_qlin);
    cudaGetSymbolAddress((void**)&klin, g_klin);
    cudaGetSymbolAddress((void**)&vlin, g_vlin);
    cudaGetSymbolAddress((void**)&qn, g_qn);
    cudaGetSymbolAddress((void**)&kn, g_kn);
    cudaGetSymbolAddress((void**)&vn, g_vn);
    cudaGetSymbolAddress((void**)&beta, g_beta);
    cudaGetSymbolAddress((void**)&eg, g_eg);
    cudaGetSymbolAddress((void**)&ob, g_o);
    cudaGetSymbolAddress((void**)&x2, g_x2);
    cudaGetSymbolAddress((void**)&gl, g_gl);
    cudaGetSymbolAddress((void**)&ul, g_ul);

    __half *xh,*xl,*hh,*hl,*onh,*onl,*h2h,*h2l,*mh,*ml;
    __half *wsgh,*wqh,*wkh,*wvh,*woh,*wgh,*wuh,*wdh;
    cudaGetSymbolAddress((void**)&xh, g_xh);   cudaGetSymbolAddress((void**)&xl, g_xl);
    cudaGetSymbolAddress((void**)&hh, g_hh);   cudaGetSymbolAddress((void**)&hl, g_hl);
    cudaGetSymbolAddress((void**)&onh, g_onh); cudaGetSymbolAddress((void**)&onl, g_onl);
    cudaGetSymbolAddress((void**)&h2h, g_h2h); cudaGetSymbolAddress((void**)&h2l, g_h2l);
    cudaGetSymbolAddress((void**)&mh, g_mh);   cudaGetSymbolAddress((void**)&ml, g_ml);
    cudaGetSymbolAddress((void**)&wsgh, g_wsgh);
    cudaGetSymbolAddress((void**)&wqh, g_wqh);
    cudaGetSymbolAddress((void**)&wkh, g_wkh);
    cudaGetSymbolAddress((void**)&wvh, g_wvh);
    cudaGetSymbolAddress((void**)&woh, g_woh);
    cudaGetSymbolAddress((void**)&wgh, g_wgh);
    cudaGetSymbolAddress((void**)&wuh, g_wuh);
    cudaGetSymbolAddress((void**)&wdh, g_wdh);

    cudaFuncSetAttribute(hm_gemm<false>, cudaFuncAttributeMaxDynamicSharedMemorySize, GSM_BYTES);
    cudaFuncSetAttribute(hm_gemm<true>,  cudaFuncAttributeMaxDynamicSharedMemorySize, GSM_BYTES);

    // launches 0-2; captured ncu slot = index 3 -> keep hm_gemm there
    k_cvtw<<<1024, 256>>>(sgw, 2*D_, D_, wsgh);        // 0
    k_cvt2<<<MT_, 256>>>(x, D_, D_, xh, xl);           // 1
    k_es<<<dim3(D_/8, B_), 256>>>(prev, spw, es);      // 2

    // ---- state fusion gate GEMM (launch 3, profiled) ----
    hm_gemm<false><<<dim3(D_/BN, MT_/BM), 256, GSM_BYTES>>>(xh, xl, wsgh, nullptr, gx, D_, D_);

    k_ge<<<dim3(D_/8, B_), 256>>>(es, sgw, sgb, ge);
    k_fuse<<<MT_*D_/256, 256>>>(x, gx, ge, es, xf);

    // ---- remaining weight conversions ----
    k_cvtw<<<1024, 256>>>(qw, D_, D_, wqh);
    k_cvtw<<<2048, 256>>>(kw, D_, D_, wkh);
    k_cvtw<<<2048, 256>>>(vw, D_, D_, wvh);
    k_cvtw<<<1024, 256>>>(ow, D_, D_, woh);
    k_cvtw<<<I_, 256>>>(gw, D_, D_, wgh);
    k_cvtw<<<I_, 256>>>(uw, D_, D_, wuh);
    k_cvtw<<<1024, 256>>>(dw, I_, I_, wdh);

    // ---- attention sub-block ----
    k_rms2<true><<<MT_, 256>>>(xf, anw, h, hh, hl);
    hm_gemm<false><<<dim3(D_/BN, MT_/BM), 256, GSM_BYTES>>>(hh, hl, wqh, nullptr, qlin, D_, D_);
    hm_gemm<false><<<dim3(2048/BN, MT_/BM), 256, GSM_BYTES>>>(hh, hl, wkh, nullptr, klin, D_, 2048);
    hm_gemm<false><<<dim3(2048/BN, MT_/BM), 256, GSM_BYTES>>>(hh, hl, wvh, nullptr, vlin, D_, 2048);
    k_ba<<<MT_, 256>>>(h, bw, aw, Alog, dtb, beta, eg);
    k_conv<true ><<<dim3(T_, H_,      B_), 256>>>(qlin, qcw, qn, H_);
    k_conv<true ><<<dim3(T_, NH_*H_, B_), 256>>>(klin, kcw, kn, NH_*H_);
    k_conv<false><<<dim3(T_, NH_*H_, B_), 256>>>(vlin, vcw, vn, NH_*H_);

    k_scan<<<B_*H_*8, 256>>>(qn, kn, vn, beta, eg, ob);

    k_onorm<<<MT_*H_, 256>>>(ob, onw, onh, onl);
    hm_gemm<true><<<dim3(D_/BN, MT_/BM), 256, GSM_BYTES>>>(onh, onl, woh, xf, x2, D_, D_);

    // ---- MLP ----
    k_rms2<false><<<MT_, 256>>>(x2, mnw, nullptr, h2h, h2l);
    hm_gemm<false><<<dim3(I_/BN, MT_/BM), 256, GSM_BYTES>>>(h2h, h2l, wgh, nullptr, gl, D_, I_);
    hm_gemm<false><<<dim3(I_/BN, MT_/BM), 256, GSM_BYTES>>>(h2h, h2l, wuh, nullptr, ul, D_, I_);
    {
        size_t n4 = (size_t)MT_*I_/4;
        k_swiglu_cvt<<<(unsigned)((n4+255)/256), 256>>>(gl, ul, mh, ml, n4);
    }
    hm_gemm<true><<<dim3(D_/BN, MT_/BM), 256, GSM_BYTES>>>(mh, ml, wdh, x2, out, I_, D_);

    // ---- second output: final hidden state ----
    k_last<<<B_*D_/256, 256>>>(out, out + (size_t)MT_*D_);
}